// round 2
// baseline (speedup 1.0000x reference)
#include <cuda_runtime.h>

// Problem constants
#define BB 32
#define SS 1024
#define EE 768
#define HH 64
#define LL 2

// Scratch (static device allocation is the sanctioned mechanism)
__device__ float g_q[(size_t)BB * SS * EE];
__device__ float g_k[(size_t)BB * SS * EE];
__device__ float g_v[(size_t)BB * SS * EE];
__device__ float g_s[(size_t)BB * SS * SS];
__device__ float g_a[(size_t)BB * SS * EE];
__device__ float g_w1t[EE * HH];

// ---------------------------------------------------------------------------
// Tiled SGEMM: C[m,n] = sum_k A[m,k] * B(k,n) + bias[n]
//   B_KMAJOR = true : B stored [N,K] row-major (C = A @ B^T)
//   B_KMAJOR = false: B stored [K,N] row-major (C = A @ B)
//   CAUSAL: skip tiles strictly above the diagonal (scores GEMM)
//   PVLIM : limit K range to m0+128 (P·V GEMM, probs are exactly 0 beyond)
// All dims assumed multiples of tile sizes (true for this problem).
// ---------------------------------------------------------------------------
template<bool B_KMAJOR, bool CAUSAL, bool PVLIM>
__global__ __launch_bounds__(256) void gemm128(
    const float* __restrict__ A, const float* __restrict__ B,
    const float* __restrict__ bias, float* __restrict__ C,
    int M, int N, int K, int lda, int ldb, int ldc,
    long long sA, long long sB, long long sC)
{
    if (CAUSAL && blockIdx.x > blockIdx.y) return;

    A += (long long)blockIdx.z * sA;
    B += (long long)blockIdx.z * sB;
    C += (long long)blockIdx.z * sC;

    const int m0 = blockIdx.y * 128;
    const int n0 = blockIdx.x * 128;
    int kend = K;
    if (PVLIM) kend = min(K, m0 + 128);

    __shared__ float As[16][132];   // +4 pad keeps float4 alignment, trims conflicts
    __shared__ float Bs[16][132];

    const int tid = threadIdx.x;
    const int tx = tid & 15;
    const int ty = tid >> 4;

    float acc[8][8];
#pragma unroll
    for (int i = 0; i < 8; i++)
#pragma unroll
        for (int j = 0; j < 8; j++) acc[i][j] = 0.f;

    for (int k0 = 0; k0 < kend; k0 += 16) {
        // A tile: 128 rows x 16 k, stored transposed As[k][m]
#pragma unroll
        for (int t = 0; t < 2; t++) {
            int v = tid + t * 256;
            int row = v >> 2;
            int kc  = (v & 3) << 2;
            const float4 a = *reinterpret_cast<const float4*>(
                &A[(long long)(m0 + row) * lda + k0 + kc]);
            As[kc + 0][row] = a.x; As[kc + 1][row] = a.y;
            As[kc + 2][row] = a.z; As[kc + 3][row] = a.w;
        }
        if (B_KMAJOR) {
#pragma unroll
            for (int t = 0; t < 2; t++) {
                int v = tid + t * 256;
                int row = v >> 2;          // n index
                int kc  = (v & 3) << 2;
                const float4 b = *reinterpret_cast<const float4*>(
                    &B[(long long)(n0 + row) * ldb + k0 + kc]);
                Bs[kc + 0][row] = b.x; Bs[kc + 1][row] = b.y;
                Bs[kc + 2][row] = b.z; Bs[kc + 3][row] = b.w;
            }
        } else {
#pragma unroll
            for (int t = 0; t < 2; t++) {
                int v = tid + t * 256;
                int kr = v >> 5;
                int nc = (v & 31) << 2;
                *reinterpret_cast<float4*>(&Bs[kr][nc]) =
                    *reinterpret_cast<const float4*>(
                        &B[(long long)(k0 + kr) * ldb + n0 + nc]);
            }
        }
        __syncthreads();

#pragma unroll
        for (int kk = 0; kk < 16; kk++) {
            float ar[8], br[8];
            *reinterpret_cast<float4*>(ar)     = *reinterpret_cast<const float4*>(&As[kk][ty * 8]);
            *reinterpret_cast<float4*>(ar + 4) = *reinterpret_cast<const float4*>(&As[kk][ty * 8 + 4]);
            *reinterpret_cast<float4*>(br)     = *reinterpret_cast<const float4*>(&Bs[kk][tx * 8]);
            *reinterpret_cast<float4*>(br + 4) = *reinterpret_cast<const float4*>(&Bs[kk][tx * 8 + 4]);
#pragma unroll
            for (int i = 0; i < 8; i++)
#pragma unroll
                for (int j = 0; j < 8; j++)
                    acc[i][j] += ar[i] * br[j];
        }
        __syncthreads();
    }

#pragma unroll
    for (int i = 0; i < 8; i++) {
        int m = m0 + ty * 8 + i;
#pragma unroll
        for (int j4 = 0; j4 < 2; j4++) {
            int n = n0 + tx * 8 + j4 * 4;
            float4 r;
            r.x = acc[i][j4 * 4 + 0]; r.y = acc[i][j4 * 4 + 1];
            r.z = acc[i][j4 * 4 + 2]; r.w = acc[i][j4 * 4 + 3];
            if (bias) {
                r.x += bias[n + 0]; r.y += bias[n + 1];
                r.z += bias[n + 2]; r.w += bias[n + 3];
            }
            *reinterpret_cast<float4*>(&C[(long long)m * ldc + n]) = r;
        }
    }
}

// ---------------------------------------------------------------------------
// Row-wise causal softmax with attention-mask additive bias.
// One block per (i, b) row of 1024. Writes the full row (masked entries
// become exactly 0.0f: exp underflow, matching fp32 reference).
// ---------------------------------------------------------------------------
__global__ __launch_bounds__(256) void softmax_causal(
    float* __restrict__ Smat, const float* __restrict__ amask)
{
    const int i = blockIdx.x;
    const int b = blockIdx.y;
    float* row = Smat + ((long long)b * SS + i) * SS;
    const float* am = amask + (long long)b * SS;
    const int tid = threadIdx.x;

    float vals[4];
    float mx = -1e30f;
#pragma unroll
    for (int r = 0; r < 4; r++) {
        int j = r * 256 + tid;
        float s = (j <= i) ? row[j] : -10000.0f;
        s += (1.0f - am[j]) * -10000.0f;
        vals[r] = s;
        mx = fmaxf(mx, s);
    }

    __shared__ float red[8];
#pragma unroll
    for (int o = 16; o > 0; o >>= 1) mx = fmaxf(mx, __shfl_xor_sync(0xffffffffu, mx, o));
    if ((tid & 31) == 0) red[tid >> 5] = mx;
    __syncthreads();
    mx = red[0];
#pragma unroll
    for (int w = 1; w < 8; w++) mx = fmaxf(mx, red[w]);

    float sum = 0.f;
#pragma unroll
    for (int r = 0; r < 4; r++) {
        vals[r] = __expf(vals[r] - mx);
        sum += vals[r];
    }
#pragma unroll
    for (int o = 16; o > 0; o >>= 1) sum += __shfl_xor_sync(0xffffffffu, sum, o);
    __syncthreads();
    if ((tid & 31) == 0) red[tid >> 5] = sum;
    __syncthreads();
    sum = 0.f;
#pragma unroll
    for (int w = 0; w < 8; w++) sum += red[w];

    const float inv = 1.0f / sum;
#pragma unroll
    for (int r = 0; r < 4; r++) row[r * 256 + tid] = vals[r] * inv;
}

// ---------------------------------------------------------------------------
// W1 [64,768] -> W1t [768,64] so the MLP reads it coalesced.
// ---------------------------------------------------------------------------
__global__ void transpose_w1(const float* __restrict__ W1, float* __restrict__ W1t)
{
    int idx = blockIdx.x * 256 + threadIdx.x;
    if (idx < HH * EE) {
        int c = idx / EE;
        int e = idx % EE;
        W1t[e * HH + c] = W1[idx];
    }
}

// ---------------------------------------------------------------------------
// Fused MLP head: out = relu(X @ W1^T + b1) @ W2^T + b2
// 4 rows per block; thread (c = t&63, rr = t>>6) computes h[rr][c].
// ---------------------------------------------------------------------------
__global__ __launch_bounds__(256) void mlp_kernel(
    const float* __restrict__ X, const float* __restrict__ W1t,
    const float* __restrict__ b1, const float* __restrict__ W2,
    const float* __restrict__ b2, float* __restrict__ out)
{
    __shared__ float xs[4][EE];
    __shared__ float hs[4][HH];
    const int row0 = blockIdx.x * 4;
    const int tid = threadIdx.x;

    for (int v = tid; v < 4 * EE; v += 256)
        xs[v / EE][v % EE] = X[(long long)(row0 + v / EE) * EE + (v % EE)];
    __syncthreads();

    const int c  = tid & 63;
    const int rr = tid >> 6;
    float a0 = 0.f, a1 = 0.f, a2 = 0.f, a3 = 0.f;
#pragma unroll 4
    for (int e = 0; e < EE; e += 4) {
        a0 += xs[rr][e + 0] * W1t[(e + 0) * HH + c];
        a1 += xs[rr][e + 1] * W1t[(e + 1) * HH + c];
        a2 += xs[rr][e + 2] * W1t[(e + 2) * HH + c];
        a3 += xs[rr][e + 3] * W1t[(e + 3) * HH + c];
    }
    float acc = b1[c] + ((a0 + a1) + (a2 + a3));
    hs[rr][c] = fmaxf(acc, 0.f);
    __syncthreads();

    if (tid < 4 * LL) {
        int r2 = tid >> 1;
        int l  = tid & 1;
        float s = b2[l];
#pragma unroll
        for (int h = 0; h < HH; h++) s += hs[r2][h] * W2[l * HH + h];
        out[(long long)(row0 + r2) * LL + l] = s;
    }
}

// ---------------------------------------------------------------------------
extern "C" void kernel_launch(void* const* d_in, const int* in_sizes, int n_in,
                              void* d_out, int out_size)
{
    const float* hidden = (const float*)d_in[0];
    const float* amask  = (const float*)d_in[1];
    const float* Wk = (const float*)d_in[2];
    const float* bk = (const float*)d_in[3];
    const float* Wq = (const float*)d_in[4];
    const float* bq = (const float*)d_in[5];
    const float* Wv = (const float*)d_in[6];
    const float* bv = (const float*)d_in[7];
    const float* W1 = (const float*)d_in[8];
    const float* b1 = (const float*)d_in[9];
    const float* W2 = (const float*)d_in[10];
    const float* b2 = (const float*)d_in[11];
    float* out = (float*)d_out;

    float *q, *k, *v, *s, *a, *w1t;
    cudaGetSymbolAddress((void**)&q,   g_q);
    cudaGetSymbolAddress((void**)&k,   g_k);
    cudaGetSymbolAddress((void**)&v,   g_v);
    cudaGetSymbolAddress((void**)&s,   g_s);
    cudaGetSymbolAddress((void**)&a,   g_a);
    cudaGetSymbolAddress((void**)&w1t, g_w1t);

    const dim3 blk(256);
    const int M = BB * SS;

    // QKV projections: C[M, E] = hidden @ W^T + b
    gemm128<true, false, false><<<dim3(EE / 128, M / 128, 1), blk>>>(
        hidden, Wq, bq, q, M, EE, EE, EE, EE, EE, 0, 0, 0);
    gemm128<true, false, false><<<dim3(EE / 128, M / 128, 1), blk>>>(
        hidden, Wk, bk, k, M, EE, EE, EE, EE, EE, 0, 0, 0);
    gemm128<true, false, false><<<dim3(EE / 128, M / 128, 1), blk>>>(
        hidden, Wv, bv, v, M, EE, EE, EE, EE, EE, 0, 0, 0);

    // W1 transpose (independent; overlaps nothing but is tiny)
    transpose_w1<<<(EE * HH + 255) / 256, blk>>>(W1, w1t);

    // Scores: s[b,i,j] = q[b,i,:] . k[b,j,:], causal tile skip
    gemm128<true, true, false><<<dim3(SS / 128, SS / 128, BB), blk>>>(
        q, k, nullptr, s, SS, SS, EE, EE, EE, SS,
        (long long)SS * EE, (long long)SS * EE, (long long)SS * SS);

    // Softmax (causal + attention-mask bias), in place
    softmax_causal<<<dim3(SS, BB), blk>>>(s, amask);

    // a[b,i,:] = p[b,i,:] @ v[b,:,:], K limited by causality
    gemm128<false, false, true><<<dim3(EE / 128, SS / 128, BB), blk>>>(
        s, v, nullptr, a, SS, EE, SS, SS, EE, EE,
        (long long)SS * SS, (long long)SS * EE, (long long)SS * EE);

    // Fused MLP head -> out [B*S, 2]
    mlp_kernel<<<M / 4, blk>>>(a, w1t, b1, W2, b2, out);
}

// round 3
// speedup vs baseline: 1.5227x; 1.5227x over previous
#include <cuda_runtime.h>
#include <cstdint>

// Problem constants
#define BB 32
#define SS 1024
#define EE 768
#define HH 64
#define LL 2

// Scratch
__device__ float g_q[(size_t)BB * SS * EE];
__device__ float g_k[(size_t)BB * SS * EE];
__device__ float g_v[(size_t)BB * SS * EE];
__device__ float g_s[(size_t)BB * SS * SS];
__device__ float g_a[(size_t)BB * SS * EE];
__device__ float g_w1t[EE * HH];

// ---------------------------------------------------------------------------
// bf16 split helpers: x ~= hi + lo, both bf16 (RNE). Dropped lo*lo ~ 2^-18.
// ---------------------------------------------------------------------------
__device__ __forceinline__ uint32_t bfr(float x) {          // f32 -> bf16 bits (RNE)
    uint32_t u = __float_as_uint(x);
    return (u + 0x7fffu + ((u >> 16) & 1u)) >> 16;
}
__device__ __forceinline__ float bff(uint32_t h) {          // bf16 bits -> f32
    return __uint_as_float(h << 16);
}
// float4 -> packed hi pair-words and lo pair-words (2 bf16 per u32, k-adjacent)
__device__ __forceinline__ void cvt4(float4 f, uint2& h, uint2& l) {
    uint32_t h0 = bfr(f.x), h1 = bfr(f.y), h2 = bfr(f.z), h3 = bfr(f.w);
    uint32_t l0 = bfr(f.x - bff(h0)), l1 = bfr(f.y - bff(h1));
    uint32_t l2 = bfr(f.z - bff(h2)), l3 = bfr(f.w - bff(h3));
    h.x = h0 | (h1 << 16); h.y = h2 | (h3 << 16);
    l.x = l0 | (l1 << 16); l.y = l2 | (l3 << 16);
}

__device__ __forceinline__ uint32_t smem_u32(const void* p) {
    return (uint32_t)__cvta_generic_to_shared(p);
}
__device__ __forceinline__ void ldm4(uint32_t* r, uint32_t addr) {
    asm volatile("ldmatrix.sync.aligned.m8n8.x4.shared.b16 {%0,%1,%2,%3}, [%4];"
                 : "=r"(r[0]), "=r"(r[1]), "=r"(r[2]), "=r"(r[3]) : "r"(addr));
}
__device__ __forceinline__ void ldm2(uint32_t* r, uint32_t addr) {
    asm volatile("ldmatrix.sync.aligned.m8n8.x2.shared.b16 {%0,%1}, [%2];"
                 : "=r"(r[0]), "=r"(r[1]) : "r"(addr));
}
__device__ __forceinline__ void mma16816(float* d, const uint32_t* a,
                                         uint32_t b0, uint32_t b1) {
    asm volatile(
        "mma.sync.aligned.m16n8k16.row.col.f32.bf16.bf16.f32 "
        "{%0,%1,%2,%3},{%4,%5,%6,%7},{%8,%9},{%0,%1,%2,%3};"
        : "+f"(d[0]), "+f"(d[1]), "+f"(d[2]), "+f"(d[3])
        : "r"(a[0]), "r"(a[1]), "r"(a[2]), "r"(a[3]), "r"(b0), "r"(b1));
}

// ---------------------------------------------------------------------------
// Tensor-core GEMM (bf16x3 split, fp32-grade accuracy):
//   C[m,n] = sum_k A[m,k]*B(k,n) + bias[n]
// Block 128x128x32, 256 threads = 8 warps (2x4), warp tile 64x32.
// Smem rows padded to 40 bf16 (80B) -> conflict-free ldmatrix.
// ---------------------------------------------------------------------------
#define KT 32
#define RS 40   // smem row stride in bf16 elems

template<bool B_KMAJOR, bool CAUSAL, bool PVLIM>
__global__ __launch_bounds__(256, 1) void gemm_mma(
    const float* __restrict__ A, const float* __restrict__ B,
    const float* __restrict__ bias, float* __restrict__ C,
    int M, int N, int K, int lda, int ldb, int ldc,
    long long sA, long long sB, long long sC)
{
    if (CAUSAL && blockIdx.x > blockIdx.y) return;

    A += (long long)blockIdx.z * sA;
    B += (long long)blockIdx.z * sB;
    C += (long long)blockIdx.z * sC;

    const int m0 = blockIdx.y * 128;
    const int n0 = blockIdx.x * 128;
    int kend = K;
    if (PVLIM) kend = min(K, m0 + 128);
    const int ktiles = kend / KT;

    __shared__ __align__(16) unsigned short Ah[128 * RS], Al[128 * RS];
    __shared__ __align__(16) unsigned short Bh[128 * RS], Bl[128 * RS];

    const int tid  = threadIdx.x;
    const int lane = tid & 31;
    const int wid  = tid >> 5;
    const int wm   = wid >> 2;   // 0..1
    const int wn   = wid & 3;    // 0..3

    // --- per-thread gmem staging coordinates (4 float4 per matrix per tile) ---
    int a_row[4], a_kq[4];
#pragma unroll
    for (int t = 0; t < 4; t++) {
        int v = tid + t * 256;           // 0..1023
        a_row[t] = v >> 3;               // 0..127
        a_kq[t]  = (v & 7) * 4;          // 0,4,...,28
    }
    int b_kr[4], b_nq[4];                // only for !B_KMAJOR
#pragma unroll
    for (int t = 0; t < 4; t++) {
        int v = tid + t * 256;
        b_kr[t] = v >> 5;                // 0..31
        b_nq[t] = (v & 31) * 4;          // 0..124
    }

    float4 ra[4], rb[4];

    auto loadTiles = [&](int k0) {
#pragma unroll
        for (int t = 0; t < 4; t++)
            ra[t] = *reinterpret_cast<const float4*>(
                &A[(long long)(m0 + a_row[t]) * lda + k0 + a_kq[t]]);
        if (B_KMAJOR) {
#pragma unroll
            for (int t = 0; t < 4; t++)
                rb[t] = *reinterpret_cast<const float4*>(
                    &B[(long long)(n0 + a_row[t]) * ldb + k0 + a_kq[t]]);
        } else {
#pragma unroll
            for (int t = 0; t < 4; t++)
                rb[t] = *reinterpret_cast<const float4*>(
                    &B[(long long)(k0 + b_kr[t]) * ldb + n0 + b_nq[t]]);
        }
    };

    auto storeTiles = [&]() {
#pragma unroll
        for (int t = 0; t < 4; t++) {
            uint2 h, l;
            cvt4(ra[t], h, l);
            int off = a_row[t] * RS + a_kq[t];
            *reinterpret_cast<uint2*>(&Ah[off]) = h;
            *reinterpret_cast<uint2*>(&Al[off]) = l;
        }
        if (B_KMAJOR) {
#pragma unroll
            for (int t = 0; t < 4; t++) {
                uint2 h, l;
                cvt4(rb[t], h, l);
                int off = a_row[t] * RS + a_kq[t];
                *reinterpret_cast<uint2*>(&Bh[off]) = h;
                *reinterpret_cast<uint2*>(&Bl[off]) = l;
            }
        } else {
#pragma unroll
            for (int t = 0; t < 4; t++) {
                const float* f = reinterpret_cast<const float*>(&rb[t]);
#pragma unroll
                for (int i = 0; i < 4; i++) {
                    uint32_t hb = bfr(f[i]);
                    uint32_t lb = bfr(f[i] - bff(hb));
                    int off = (b_nq[t] + i) * RS + b_kr[t];
                    Bh[off] = (unsigned short)hb;
                    Bl[off] = (unsigned short)lb;
                }
            }
        }
    };

    // --- fragment addressing ---
    const uint32_t aHiB = smem_u32(Ah), aLoB = smem_u32(Al);
    const uint32_t bHiB = smem_u32(Bh), bLoB = smem_u32(Bl);
    const int arow0 = wm * 64 + (lane & 7) + ((lane >> 3) & 1) * 8;
    const int acolS = ((lane >> 4) & 1) * 8;
    const int brow0 = wn * 32 + (lane & 7);
    const int bcolS = ((lane >> 3) & 1) * 8;

    float acc[4][4][4];
#pragma unroll
    for (int i = 0; i < 4; i++)
#pragma unroll
        for (int j = 0; j < 4; j++)
#pragma unroll
            for (int c = 0; c < 4; c++) acc[i][j][c] = 0.f;

    loadTiles(0);

    for (int kt = 0; kt < ktiles; kt++) {
        storeTiles();
        __syncthreads();
        if (kt + 1 < ktiles) loadTiles((kt + 1) * KT);   // LDGs in flight over MMA

#pragma unroll
        for (int ks = 0; ks < 2; ks++) {
            uint32_t ah[4][4], al[4][4], bh[4][2], bl[4][2];
            const int acol = ks * 16 + acolS;
            const int bcol = ks * 16 + bcolS;
#pragma unroll
            for (int mt = 0; mt < 4; mt++) {
                uint32_t off = ((arow0 + mt * 16) * RS + acol) * 2;
                ldm4(ah[mt], aHiB + off);
                ldm4(al[mt], aLoB + off);
            }
#pragma unroll
            for (int nt = 0; nt < 4; nt++) {
                uint32_t off = ((brow0 + nt * 8) * RS + bcol) * 2;
                ldm2(bh[nt], bHiB + off);
                ldm2(bl[nt], bLoB + off);
            }
#pragma unroll
            for (int mt = 0; mt < 4; mt++)
#pragma unroll
                for (int nt = 0; nt < 4; nt++) {
                    mma16816(acc[mt][nt], ah[mt], bh[nt][0], bh[nt][1]);
                    mma16816(acc[mt][nt], ah[mt], bl[nt][0], bl[nt][1]);
                    mma16816(acc[mt][nt], al[mt], bh[nt][0], bh[nt][1]);
                }
        }
        __syncthreads();
    }

    // --- epilogue ---
#pragma unroll
    for (int mt = 0; mt < 4; mt++) {
        int m = m0 + wm * 64 + mt * 16 + (lane >> 2);
#pragma unroll
        for (int nt = 0; nt < 4; nt++) {
            int n = n0 + wn * 32 + nt * 8 + (lane & 3) * 2;
            float b0 = 0.f, b1 = 0.f;
            if (bias) { b0 = bias[n]; b1 = bias[n + 1]; }
            float2 v0 = {acc[mt][nt][0] + b0, acc[mt][nt][1] + b1};
            float2 v1 = {acc[mt][nt][2] + b0, acc[mt][nt][3] + b1};
            *reinterpret_cast<float2*>(&C[(long long)m * ldc + n]) = v0;
            *reinterpret_cast<float2*>(&C[(long long)(m + 8) * ldc + n]) = v1;
        }
    }
}

// ---------------------------------------------------------------------------
// Row-wise causal softmax with attention-mask additive bias.
// ---------------------------------------------------------------------------
__global__ __launch_bounds__(256) void softmax_causal(
    float* __restrict__ Smat, const float* __restrict__ amask)
{
    const int i = blockIdx.x;
    const int b = blockIdx.y;
    float* row = Smat + ((long long)b * SS + i) * SS;
    const float* am = amask + (long long)b * SS;
    const int tid = threadIdx.x;

    float vals[4];
    float mx = -1e30f;
#pragma unroll
    for (int r = 0; r < 4; r++) {
        int j = r * 256 + tid;
        float s = (j <= i) ? row[j] : -10000.0f;
        s += (1.0f - am[j]) * -10000.0f;
        vals[r] = s;
        mx = fmaxf(mx, s);
    }

    __shared__ float red[8];
#pragma unroll
    for (int o = 16; o > 0; o >>= 1) mx = fmaxf(mx, __shfl_xor_sync(0xffffffffu, mx, o));
    if ((tid & 31) == 0) red[tid >> 5] = mx;
    __syncthreads();
    mx = red[0];
#pragma unroll
    for (int w = 1; w < 8; w++) mx = fmaxf(mx, red[w]);

    float sum = 0.f;
#pragma unroll
    for (int r = 0; r < 4; r++) {
        vals[r] = __expf(vals[r] - mx);
        sum += vals[r];
    }
#pragma unroll
    for (int o = 16; o > 0; o >>= 1) sum += __shfl_xor_sync(0xffffffffu, sum, o);
    __syncthreads();
    if ((tid & 31) == 0) red[tid >> 5] = sum;
    __syncthreads();
    sum = 0.f;
#pragma unroll
    for (int w = 0; w < 8; w++) sum += red[w];

    const float inv = 1.0f / sum;
#pragma unroll
    for (int r = 0; r < 4; r++) row[r * 256 + tid] = vals[r] * inv;
}

// ---------------------------------------------------------------------------
__global__ void transpose_w1(const float* __restrict__ W1, float* __restrict__ W1t)
{
    int idx = blockIdx.x * 256 + threadIdx.x;
    if (idx < HH * EE) {
        int c = idx / EE;
        int e = idx % EE;
        W1t[e * HH + c] = W1[idx];
    }
}

// ---------------------------------------------------------------------------
// Fused MLP head: out = relu(X @ W1^T + b1) @ W2^T + b2
// ---------------------------------------------------------------------------
__global__ __launch_bounds__(256) void mlp_kernel(
    const float* __restrict__ X, const float* __restrict__ W1t,
    const float* __restrict__ b1, const float* __restrict__ W2,
    const float* __restrict__ b2, float* __restrict__ out)
{
    __shared__ float xs[4][EE];
    __shared__ float hs[4][HH];
    const int row0 = blockIdx.x * 4;
    const int tid = threadIdx.x;

    for (int v = tid; v < 4 * EE; v += 256)
        xs[v / EE][v % EE] = X[(long long)(row0 + v / EE) * EE + (v % EE)];
    __syncthreads();

    const int c  = tid & 63;
    const int rr = tid >> 6;
    float a0 = 0.f, a1 = 0.f, a2 = 0.f, a3 = 0.f;
#pragma unroll 4
    for (int e = 0; e < EE; e += 4) {
        a0 += xs[rr][e + 0] * W1t[(e + 0) * HH + c];
        a1 += xs[rr][e + 1] * W1t[(e + 1) * HH + c];
        a2 += xs[rr][e + 2] * W1t[(e + 2) * HH + c];
        a3 += xs[rr][e + 3] * W1t[(e + 3) * HH + c];
    }
    float acc = b1[c] + ((a0 + a1) + (a2 + a3));
    hs[rr][c] = fmaxf(acc, 0.f);
    __syncthreads();

    if (tid < 4 * LL) {
        int r2 = tid >> 1;
        int l  = tid & 1;
        float s = b2[l];
#pragma unroll
        for (int h = 0; h < HH; h++) s += hs[r2][h] * W2[l * HH + h];
        out[(long long)(row0 + r2) * LL + l] = s;
    }
}

// ---------------------------------------------------------------------------
extern "C" void kernel_launch(void* const* d_in, const int* in_sizes, int n_in,
                              void* d_out, int out_size)
{
    const float* hidden = (const float*)d_in[0];
    const float* amask  = (const float*)d_in[1];
    const float* Wk = (const float*)d_in[2];
    const float* bk = (const float*)d_in[3];
    const float* Wq = (const float*)d_in[4];
    const float* bq = (const float*)d_in[5];
    const float* Wv = (const float*)d_in[6];
    const float* bv = (const float*)d_in[7];
    const float* W1 = (const float*)d_in[8];
    const float* b1 = (const float*)d_in[9];
    const float* W2 = (const float*)d_in[10];
    const float* b2 = (const float*)d_in[11];
    float* out = (float*)d_out;

    float *q, *k, *v, *s, *a, *w1t;
    cudaGetSymbolAddress((void**)&q,   g_q);
    cudaGetSymbolAddress((void**)&k,   g_k);
    cudaGetSymbolAddress((void**)&v,   g_v);
    cudaGetSymbolAddress((void**)&s,   g_s);
    cudaGetSymbolAddress((void**)&a,   g_a);
    cudaGetSymbolAddress((void**)&w1t, g_w1t);

    const dim3 blk(256);
    const int M = BB * SS;

    // QKV projections: C[M, E] = hidden @ W^T + b  (bf16x3 tensor-core)
    gemm_mma<true, false, false><<<dim3(EE / 128, M / 128, 1), blk>>>(
        hidden, Wq, bq, q, M, EE, EE, EE, EE, EE, 0, 0, 0);
    gemm_mma<true, false, false><<<dim3(EE / 128, M / 128, 1), blk>>>(
        hidden, Wk, bk, k, M, EE, EE, EE, EE, EE, 0, 0, 0);
    gemm_mma<true, false, false><<<dim3(EE / 128, M / 128, 1), blk>>>(
        hidden, Wv, bv, v, M, EE, EE, EE, EE, EE, 0, 0, 0);

    transpose_w1<<<(EE * HH + 255) / 256, blk>>>(W1, w1t);

    // Scores: s[b,i,j] = q[b,i,:] . k[b,j,:], causal tile skip
    gemm_mma<true, true, false><<<dim3(SS / 128, SS / 128, BB), blk>>>(
        q, k, nullptr, s, SS, SS, EE, EE, EE, SS,
        (long long)SS * EE, (long long)SS * EE, (long long)SS * SS);

    // Softmax (causal + attention-mask bias), in place
    softmax_causal<<<dim3(SS, BB), blk>>>(s, amask);

    // a[b,i,:] = p[b,i,:] @ v[b,:,:], K limited by causality
    gemm_mma<false, false, true><<<dim3(EE / 128, SS / 128, BB), blk>>>(
        s, v, nullptr, a, SS, EE, SS, SS, EE, EE,
        (long long)SS * SS, (long long)SS * EE, (long long)SS * EE);

    // Fused MLP head -> out [B*S, 2]
    mlp_kernel<<<M / 4, blk>>>(a, w1t, b1, W2, b2, out);
}

// round 4
// speedup vs baseline: 1.6053x; 1.0543x over previous
#include <cuda_runtime.h>
#include <cstdint>

// Problem constants
#define BB 32
#define SS 1024
#define EE 768
#define HH 64
#define LL 2

// Scratch
__device__ float g_q[(size_t)BB * SS * EE];
__device__ float g_k[(size_t)BB * SS * EE];
__device__ float g_v[(size_t)BB * SS * EE];
__device__ float g_s[(size_t)BB * SS * SS];
__device__ float g_a[(size_t)BB * SS * EE];
__device__ float g_w1t[EE * HH];

// ---------------------------------------------------------------------------
// bf16 split helpers
// ---------------------------------------------------------------------------
__device__ __forceinline__ uint32_t bfr(float x) {
    uint32_t u = __float_as_uint(x);
    return (u + 0x7fffu + ((u >> 16) & 1u)) >> 16;
}
__device__ __forceinline__ float bff(uint32_t h) {
    return __uint_as_float(h << 16);
}
__device__ __forceinline__ void cvt4(float4 f, uint2& h, uint2& l) {
    uint32_t h0 = bfr(f.x), h1 = bfr(f.y), h2 = bfr(f.z), h3 = bfr(f.w);
    uint32_t l0 = bfr(f.x - bff(h0)), l1 = bfr(f.y - bff(h1));
    uint32_t l2 = bfr(f.z - bff(h2)), l3 = bfr(f.w - bff(h3));
    h.x = h0 | (h1 << 16); h.y = h2 | (h3 << 16);
    l.x = l0 | (l1 << 16); l.y = l2 | (l3 << 16);
}
__device__ __forceinline__ uint32_t smem_u32(const void* p) {
    return (uint32_t)__cvta_generic_to_shared(p);
}
__device__ __forceinline__ void ldm4(uint32_t* r, uint32_t addr) {
    asm volatile("ldmatrix.sync.aligned.m8n8.x4.shared.b16 {%0,%1,%2,%3}, [%4];"
                 : "=r"(r[0]), "=r"(r[1]), "=r"(r[2]), "=r"(r[3]) : "r"(addr));
}
__device__ __forceinline__ void mma16816(float* d, const uint32_t* a,
                                         uint32_t b0, uint32_t b1) {
    asm volatile(
        "mma.sync.aligned.m16n8k16.row.col.f32.bf16.bf16.f32 "
        "{%0,%1,%2,%3},{%4,%5,%6,%7},{%8,%9},{%0,%1,%2,%3};"
        : "+f"(d[0]), "+f"(d[1]), "+f"(d[2]), "+f"(d[3])
        : "r"(a[0]), "r"(a[1]), "r"(a[2]), "r"(a[3]), "r"(b0), "r"(b1));
}

// ---------------------------------------------------------------------------
// Tensor-core GEMM (bf16x3 split): C[m,n] = sum_k A[m,k]*B(k,n) + bias[n]
// Block 128x256x32, 256 threads = 8 warps (2x4), warp tile 64x64.
// Double-buffered dynamic smem, rows padded to 40 bf16 -> conflict-free LDSM.
// ---------------------------------------------------------------------------
#define KT 32
#define RS 40
#define STG (768 * RS)          // bf16 elems per stage (A:2*128 rows, B:2*256 rows)
#define OFF_AH 0
#define OFF_AL (128 * RS)
#define OFF_BH (256 * RS)
#define OFF_BL (512 * RS)
#define SMEM_BYTES (2 * STG * 2)

template<bool B_KMAJOR, bool CAUSAL, bool PVLIM>
__global__ __launch_bounds__(256, 1) void gemm_mma(
    const float* __restrict__ A, const float* __restrict__ B,
    const float* __restrict__ bias, float* __restrict__ C,
    int M, int N, int K, int lda, int ldb, int ldc,
    long long sA, long long sB, long long sC)
{
    const int n0 = blockIdx.x * 256;
    const int m0 = blockIdx.y * 128;
    if (CAUSAL && n0 >= m0 + 128) return;

    A += (long long)blockIdx.z * sA;
    B += (long long)blockIdx.z * sB;
    C += (long long)blockIdx.z * sC;

    int kend = K;
    if (PVLIM) kend = min(K, m0 + 128);
    const int ktiles = kend / KT;

    extern __shared__ __align__(16) unsigned short sm[];

    const int tid  = threadIdx.x;
    const int lane = tid & 31;
    const int wid  = tid >> 5;
    const int wm   = wid >> 2;   // 0..1
    const int wn   = wid & 3;    // 0..3

    float4 ra[4], rb[8];

    auto loadT = [&](int k0) {
#pragma unroll
        for (int t = 0; t < 4; t++) {
            int v = tid + t * 256;
            ra[t] = *reinterpret_cast<const float4*>(
                &A[(long long)(m0 + (v >> 3)) * lda + k0 + (v & 7) * 4]);
        }
        if (B_KMAJOR) {
#pragma unroll
            for (int t = 0; t < 8; t++) {
                int v = tid + t * 256;
                rb[t] = *reinterpret_cast<const float4*>(
                    &B[(long long)(n0 + (v >> 3)) * ldb + k0 + (v & 7) * 4]);
            }
        } else {
#pragma unroll
            for (int t = 0; t < 8; t++) {
                int v = tid + t * 256;
                rb[t] = *reinterpret_cast<const float4*>(
                    &B[(long long)(k0 + (v >> 6)) * ldb + n0 + (v & 63) * 4]);
            }
        }
    };

    auto storeT = [&](int s) {
        unsigned short* base = sm + s * STG;
#pragma unroll
        for (int t = 0; t < 4; t++) {
            int v = tid + t * 256;
            uint2 h, l;
            cvt4(ra[t], h, l);
            int off = (v >> 3) * RS + (v & 7) * 4;
            *reinterpret_cast<uint2*>(base + OFF_AH + off) = h;
            *reinterpret_cast<uint2*>(base + OFF_AL + off) = l;
        }
        if (B_KMAJOR) {
#pragma unroll
            for (int t = 0; t < 8; t++) {
                int v = tid + t * 256;
                uint2 h, l;
                cvt4(rb[t], h, l);
                int off = (v >> 3) * RS + (v & 7) * 4;
                *reinterpret_cast<uint2*>(base + OFF_BH + off) = h;
                *reinterpret_cast<uint2*>(base + OFF_BL + off) = l;
            }
        } else {
#pragma unroll
            for (int t = 0; t < 8; t++) {
                int v = tid + t * 256;
                int kr = v >> 6;
                int nq = (v & 63) * 4;
                const float* f = reinterpret_cast<const float*>(&rb[t]);
#pragma unroll
                for (int i = 0; i < 4; i++) {
                    uint32_t hb = bfr(f[i]);
                    uint32_t lb = bfr(f[i] - bff(hb));
                    int off = (nq + i) * RS + kr;
                    base[OFF_BH + off] = (unsigned short)hb;
                    base[OFF_BL + off] = (unsigned short)lb;
                }
            }
        }
    };

    // fragment addressing (conflict-free: 80B row stride)
    const uint32_t smB = smem_u32(sm);
    const int aRow  = wm * 64 + (lane & 7) + ((lane >> 3) & 1) * 8;
    const int aColS = ((lane >> 4) & 1) * 8;
    const int bRow  = wn * 64 + (lane & 7) + ((lane >> 4) & 1) * 8;
    const int bColS = ((lane >> 3) & 1) * 8;

    float acc[4][8][4];
#pragma unroll
    for (int i = 0; i < 4; i++)
#pragma unroll
        for (int j = 0; j < 8; j++)
#pragma unroll
            for (int c = 0; c < 4; c++) acc[i][j][c] = 0.f;

    loadT(0);
    storeT(0);
    __syncthreads();

    int s = 0;
    for (int kt = 0; kt < ktiles; kt++) {
        const bool more = (kt + 1 < ktiles);
        if (more) loadT((kt + 1) * KT);          // LDGs fly over the MMA phase

        const uint32_t stB = smB + (uint32_t)s * (STG * 2);
#pragma unroll
        for (int ks = 0; ks < 2; ks++) {
            uint32_t ah[4][4], al[4][4];
#pragma unroll
            for (int mt = 0; mt < 4; mt++) {
                uint32_t off = (uint32_t)(((aRow + mt * 16) * RS) + ks * 16 + aColS) * 2;
                ldm4(ah[mt], stB + OFF_AH * 2 + off);
                ldm4(al[mt], stB + OFF_AL * 2 + off);
            }
#pragma unroll
            for (int np = 0; np < 4; np++) {
                uint32_t bh[4], bl[4];
                uint32_t off = (uint32_t)(((bRow + np * 16) * RS) + ks * 16 + bColS) * 2;
                ldm4(bh, stB + OFF_BH * 2 + off);
                ldm4(bl, stB + OFF_BL * 2 + off);
#pragma unroll
                for (int h = 0; h < 2; h++) {
                    const int nt = np * 2 + h;
#pragma unroll
                    for (int mt = 0; mt < 4; mt++) {
                        mma16816(acc[mt][nt], ah[mt], bh[2 * h], bh[2 * h + 1]);
                        mma16816(acc[mt][nt], ah[mt], bl[2 * h], bl[2 * h + 1]);
                        mma16816(acc[mt][nt], al[mt], bh[2 * h], bh[2 * h + 1]);
                    }
                }
            }
        }
        if (more) storeT(s ^ 1);
        __syncthreads();
        s ^= 1;
    }

    // epilogue
#pragma unroll
    for (int mt = 0; mt < 4; mt++) {
        int m = m0 + wm * 64 + mt * 16 + (lane >> 2);
#pragma unroll
        for (int nt = 0; nt < 8; nt++) {
            int n = n0 + wn * 64 + nt * 8 + (lane & 3) * 2;
            float b0 = 0.f, b1 = 0.f;
            if (bias) { b0 = bias[n]; b1 = bias[n + 1]; }
            float2 v0 = {acc[mt][nt][0] + b0, acc[mt][nt][1] + b1};
            float2 v1 = {acc[mt][nt][2] + b0, acc[mt][nt][3] + b1};
            *reinterpret_cast<float2*>(&C[(long long)m * ldc + n]) = v0;
            *reinterpret_cast<float2*>(&C[(long long)(m + 8) * ldc + n]) = v1;
        }
    }
}

// ---------------------------------------------------------------------------
// Row-wise causal softmax with attention-mask additive bias.
// ---------------------------------------------------------------------------
__global__ __launch_bounds__(256) void softmax_causal(
    float* __restrict__ Smat, const float* __restrict__ amask)
{
    const int i = blockIdx.x;
    const int b = blockIdx.y;
    float* row = Smat + ((long long)b * SS + i) * SS;
    const float* am = amask + (long long)b * SS;
    const int tid = threadIdx.x;

    float vals[4];
    float mx = -1e30f;
#pragma unroll
    for (int r = 0; r < 4; r++) {
        int j = r * 256 + tid;
        float s = (j <= i) ? row[j] : -10000.0f;
        s += (1.0f - am[j]) * -10000.0f;
        vals[r] = s;
        mx = fmaxf(mx, s);
    }

    __shared__ float red[8];
#pragma unroll
    for (int o = 16; o > 0; o >>= 1) mx = fmaxf(mx, __shfl_xor_sync(0xffffffffu, mx, o));
    if ((tid & 31) == 0) red[tid >> 5] = mx;
    __syncthreads();
    mx = red[0];
#pragma unroll
    for (int w = 1; w < 8; w++) mx = fmaxf(mx, red[w]);

    float sum = 0.f;
#pragma unroll
    for (int r = 0; r < 4; r++) {
        vals[r] = __expf(vals[r] - mx);
        sum += vals[r];
    }
#pragma unroll
    for (int o = 16; o > 0; o >>= 1) sum += __shfl_xor_sync(0xffffffffu, sum, o);
    __syncthreads();
    if ((tid & 31) == 0) red[tid >> 5] = sum;
    __syncthreads();
    sum = 0.f;
#pragma unroll
    for (int w = 0; w < 8; w++) sum += red[w];

    const float inv = 1.0f / sum;
#pragma unroll
    for (int r = 0; r < 4; r++) row[r * 256 + tid] = vals[r] * inv;
}

// ---------------------------------------------------------------------------
__global__ void transpose_w1(const float* __restrict__ W1, float* __restrict__ W1t)
{
    int idx = blockIdx.x * 256 + threadIdx.x;
    if (idx < HH * EE) {
        int c = idx / EE;
        int e = idx % EE;
        W1t[e * HH + c] = W1[idx];
    }
}

// ---------------------------------------------------------------------------
// Fused MLP head: out = relu(X @ W1^T + b1) @ W2^T + b2
// ---------------------------------------------------------------------------
__global__ __launch_bounds__(256) void mlp_kernel(
    const float* __restrict__ X, const float* __restrict__ W1t,
    const float* __restrict__ b1, const float* __restrict__ W2,
    const float* __restrict__ b2, float* __restrict__ out)
{
    __shared__ float xs[4][EE];
    __shared__ float hs[4][HH];
    const int row0 = blockIdx.x * 4;
    const int tid = threadIdx.x;

    for (int v = tid; v < 4 * EE; v += 256)
        xs[v / EE][v % EE] = X[(long long)(row0 + v / EE) * EE + (v % EE)];
    __syncthreads();

    const int c  = tid & 63;
    const int rr = tid >> 6;
    float a0 = 0.f, a1 = 0.f, a2 = 0.f, a3 = 0.f;
#pragma unroll 4
    for (int e = 0; e < EE; e += 4) {
        a0 += xs[rr][e + 0] * W1t[(e + 0) * HH + c];
        a1 += xs[rr][e + 1] * W1t[(e + 1) * HH + c];
        a2 += xs[rr][e + 2] * W1t[(e + 2) * HH + c];
        a3 += xs[rr][e + 3] * W1t[(e + 3) * HH + c];
    }
    float acc = b1[c] + ((a0 + a1) + (a2 + a3));
    hs[rr][c] = fmaxf(acc, 0.f);
    __syncthreads();

    if (tid < 4 * LL) {
        int r2 = tid >> 1;
        int l  = tid & 1;
        float s = b2[l];
#pragma unroll
        for (int h = 0; h < HH; h++) s += hs[r2][h] * W2[l * HH + h];
        out[(long long)(row0 + r2) * LL + l] = s;
    }
}

// ---------------------------------------------------------------------------
extern "C" void kernel_launch(void* const* d_in, const int* in_sizes, int n_in,
                              void* d_out, int out_size)
{
    const float* hidden = (const float*)d_in[0];
    const float* amask  = (const float*)d_in[1];
    const float* Wk = (const float*)d_in[2];
    const float* bk = (const float*)d_in[3];
    const float* Wq = (const float*)d_in[4];
    const float* bq = (const float*)d_in[5];
    const float* Wv = (const float*)d_in[6];
    const float* bv = (const float*)d_in[7];
    const float* W1 = (const float*)d_in[8];
    const float* b1 = (const float*)d_in[9];
    const float* W2 = (const float*)d_in[10];
    const float* b2 = (const float*)d_in[11];
    float* out = (float*)d_out;

    float *q, *k, *v, *s, *a, *w1t;
    cudaGetSymbolAddress((void**)&q,   g_q);
    cudaGetSymbolAddress((void**)&k,   g_k);
    cudaGetSymbolAddress((void**)&v,   g_v);
    cudaGetSymbolAddress((void**)&s,   g_s);
    cudaGetSymbolAddress((void**)&a,   g_a);
    cudaGetSymbolAddress((void**)&w1t, g_w1t);

    cudaFuncSetAttribute((const void*)gemm_mma<true,  false, false>,
                         cudaFuncAttributeMaxDynamicSharedMemorySize, SMEM_BYTES);
    cudaFuncSetAttribute((const void*)gemm_mma<true,  true,  false>,
                         cudaFuncAttributeMaxDynamicSharedMemorySize, SMEM_BYTES);
    cudaFuncSetAttribute((const void*)gemm_mma<false, false, true>,
                         cudaFuncAttributeMaxDynamicSharedMemorySize, SMEM_BYTES);

    const dim3 blk(256);
    const int M = BB * SS;

    // QKV projections: C[M, E] = hidden @ W^T + b
    gemm_mma<true, false, false><<<dim3(EE / 256, M / 128, 1), blk, SMEM_BYTES>>>(
        hidden, Wq, bq, q, M, EE, EE, EE, EE, EE, 0, 0, 0);
    gemm_mma<true, false, false><<<dim3(EE / 256, M / 128, 1), blk, SMEM_BYTES>>>(
        hidden, Wk, bk, k, M, EE, EE, EE, EE, EE, 0, 0, 0);
    gemm_mma<true, false, false><<<dim3(EE / 256, M / 128, 1), blk, SMEM_BYTES>>>(
        hidden, Wv, bv, v, M, EE, EE, EE, EE, EE, 0, 0, 0);

    transpose_w1<<<(EE * HH + 255) / 256, blk>>>(W1, w1t);

    // Scores: s[b,i,j] = q[b,i,:] . k[b,j,:], causal tile skip
    gemm_mma<true, true, false><<<dim3(SS / 256, SS / 128, BB), blk, SMEM_BYTES>>>(
        q, k, nullptr, s, SS, SS, EE, EE, EE, SS,
        (long long)SS * EE, (long long)SS * EE, (long long)SS * SS);

    // Softmax (causal + attention-mask bias), in place
    softmax_causal<<<dim3(SS, BB), blk>>>(s, amask);

    // a[b,i,:] = p[b,i,:] @ v[b,:,:], K limited by causality
    gemm_mma<false, false, true><<<dim3(EE / 256, SS / 128, BB), blk, SMEM_BYTES>>>(
        s, v, nullptr, a, SS, EE, SS, SS, EE, EE,
        (long long)SS * SS, (long long)SS * EE, (long long)SS * EE);

    // Fused MLP head -> out [B*S, 2]
    mlp_kernel<<<M / 4, blk>>>(a, w1t, b1, W2, b2, out);
}

// round 7
// speedup vs baseline: 1.9538x; 1.2171x over previous
#include <cuda_runtime.h>
#include <cstdint>

// Problem constants
#define BB 32
#define SS 1024
#define EE 768
#define HH 64
#define LL 2
#define MM (BB * SS)

typedef unsigned short u16;

// ---------------------------------------------------------------------------
// Scratch (static device allocations)
// ---------------------------------------------------------------------------
__device__ u16  g_hid_h[(size_t)MM * EE], g_hid_l[(size_t)MM * EE];
__device__ u16  g_wq_h[EE * EE], g_wq_l[EE * EE];
__device__ u16  g_wk_h[EE * EE], g_wk_l[EE * EE];
__device__ u16  g_wv_h[EE * EE], g_wv_l[EE * EE];
__device__ u16  g_q_h[(size_t)MM * EE], g_q_l[(size_t)MM * EE];
__device__ u16  g_k_h[(size_t)MM * EE], g_k_l[(size_t)MM * EE];
__device__ u16  g_v_h[(size_t)MM * EE], g_v_l[(size_t)MM * EE];
__device__ u16  g_p_h[(size_t)BB * SS * SS], g_p_l[(size_t)BB * SS * SS];
__device__ float g_s[(size_t)BB * SS * SS];
__device__ float g_a[(size_t)MM * EE];
__device__ float g_w1t[EE * HH];

// ---------------------------------------------------------------------------
// helpers
// ---------------------------------------------------------------------------
__device__ __forceinline__ uint32_t smem_u32(const void* p) {
    return (uint32_t)__cvta_generic_to_shared(p);
}
__device__ __forceinline__ void ldm4(uint32_t* r, uint32_t addr) {
    asm volatile("ldmatrix.sync.aligned.m8n8.x4.shared.b16 {%0,%1,%2,%3}, [%4];"
                 : "=r"(r[0]), "=r"(r[1]), "=r"(r[2]), "=r"(r[3]) : "r"(addr));
}
__device__ __forceinline__ void ldm4t(uint32_t* r, uint32_t addr) {
    asm volatile("ldmatrix.sync.aligned.m8n8.x4.trans.shared.b16 {%0,%1,%2,%3}, [%4];"
                 : "=r"(r[0]), "=r"(r[1]), "=r"(r[2]), "=r"(r[3]) : "r"(addr));
}
__device__ __forceinline__ void mma16816(float* d, const uint32_t* a,
                                         uint32_t b0, uint32_t b1) {
    asm volatile(
        "mma.sync.aligned.m16n8k16.row.col.f32.bf16.bf16.f32 "
        "{%0,%1,%2,%3},{%4,%5,%6,%7},{%8,%9},{%0,%1,%2,%3};"
        : "+f"(d[0]), "+f"(d[1]), "+f"(d[2]), "+f"(d[3])
        : "r"(a[0]), "r"(a[1]), "r"(a[2]), "r"(a[3]), "r"(b0), "r"(b1));
}
// hardware f32 pair -> bf16x2 (hi) + residual bf16x2 (lo); lo half = first arg
__device__ __forceinline__ uint32_t pack2(float a, float b) {
    uint32_t r;
    asm("cvt.rn.bf16x2.f32 %0, %1, %2;" : "=r"(r) : "f"(b), "f"(a));
    return r;
}
__device__ __forceinline__ void cvt_hl(float a, float b, uint32_t& h, uint32_t& l) {
    h = pack2(a, b);
    float ha = __uint_as_float(h << 16);
    float hb = __uint_as_float(h & 0xffff0000u);
    l = pack2(a - ha, b - hb);
}

// ---------------------------------------------------------------------------
// One-time f32 -> (hi, lo) bf16 split, vectorized
// ---------------------------------------------------------------------------
__global__ void split_f32(const float4* __restrict__ x, uint2* __restrict__ h,
                          uint2* __restrict__ l, int n4)
{
    for (int i = blockIdx.x * blockDim.x + threadIdx.x; i < n4;
         i += gridDim.x * blockDim.x) {
        float4 f = x[i];
        uint2 hh, ll;
        cvt_hl(f.x, f.y, hh.x, ll.x);
        cvt_hl(f.z, f.w, hh.y, ll.y);
        h[i] = hh; l[i] = ll;
    }
}

// ---------------------------------------------------------------------------
// Split-bf16 tensor-core GEMM: C[m,n] = sum_k A[m,k]*B(k,n) + bias[n]
// Operands pre-split into hi/lo bf16 in gmem; hot loop = LDG/STS/LDSM/HMMA.
//   BTRANS=false: B K-major [n][k];  BTRANS=true: B [k][n] (PV), ldmatrix.trans
//   SPLITOUT: epilogue emits hi/lo bf16 arrays instead of f32
// Block 128x256x32, 8 warps (2x4), warp 64x64, double-buffered.
// ---------------------------------------------------------------------------
#define RSA 40     // A (and K-major B) smem row stride, u16
#define RSBT 264   // trans-B smem row stride, u16

template<bool BTRANS, bool CAUSAL, bool PVLIM, bool SPLITOUT>
__global__ __launch_bounds__(256, 1) void gemm_bf16(
    const u16* __restrict__ Agh, const u16* __restrict__ Agl,
    const u16* __restrict__ Bgh, const u16* __restrict__ Bgl,
    const float* __restrict__ bias,
    float* __restrict__ Cf, u16* __restrict__ Ch, u16* __restrict__ Cl,
    int K, int lda, int ldb, int ldc,
    long long sA, long long sB, long long sC)
{
    const int n0 = blockIdx.x * 256;
    const int m0 = blockIdx.y * 128;
    if (CAUSAL && n0 >= m0 + 128) return;

    Agh += (long long)blockIdx.z * sA; Agl += (long long)blockIdx.z * sA;
    Bgh += (long long)blockIdx.z * sB; Bgl += (long long)blockIdx.z * sB;
    if (SPLITOUT) {
        Ch += (long long)blockIdx.z * sC; Cl += (long long)blockIdx.z * sC;
    } else {
        Cf += (long long)blockIdx.z * sC;
    }

    int kend = PVLIM ? (m0 + 128) : K;
    const int ktiles = kend / 32;

    constexpr int ASZ = 128 * RSA;
    constexpr int BSZ = BTRANS ? 32 * RSBT : 256 * RSA;
    constexpr int OAh = 0, OAl = ASZ, OBh = 2 * ASZ, OBl = 2 * ASZ + BSZ;
    constexpr int STGU = 2 * ASZ + 2 * BSZ;

    extern __shared__ __align__(16) u16 sm[];

    const int tid  = threadIdx.x;
    const int lane = tid & 31;
    const int wid  = tid >> 5;
    const int wm   = wid >> 2;   // 0..1
    const int wn   = wid & 3;    // 0..3

    uint4 rah[2], ral[2], rbh[4], rbl[4];

    auto loadT = [&](int k0) {
#pragma unroll
        for (int t = 0; t < 2; t++) {
            const int v = tid + t * 256;           // 0..511
            const size_t g = (size_t)(m0 + (v >> 2)) * lda + k0 + (v & 3) * 8;
            rah[t] = *reinterpret_cast<const uint4*>(Agh + g);
            ral[t] = *reinterpret_cast<const uint4*>(Agl + g);
        }
        if (!BTRANS) {
#pragma unroll
            for (int t = 0; t < 4; t++) {
                const int v = tid + t * 256;       // 0..1023
                const size_t g = (size_t)(n0 + (v >> 2)) * ldb + k0 + (v & 3) * 8;
                rbh[t] = *reinterpret_cast<const uint4*>(Bgh + g);
                rbl[t] = *reinterpret_cast<const uint4*>(Bgl + g);
            }
        } else {
            // k-tile: 32 rows x 256 cols -> 1024 uint4; row = v>>5, col = (v&31)*8
#pragma unroll
            for (int t = 0; t < 4; t++) {
                const int v = tid + t * 256;
                const size_t g = (size_t)(k0 + (v >> 5)) * ldb + n0 + (v & 31) * 8;
                rbh[t] = *reinterpret_cast<const uint4*>(Bgh + g);
                rbl[t] = *reinterpret_cast<const uint4*>(Bgl + g);
            }
        }
    };

    auto storeT = [&](int s) {
        u16* base = sm + s * STGU;
#pragma unroll
        for (int t = 0; t < 2; t++) {
            const int v = tid + t * 256;
            const int off = (v >> 2) * RSA + (v & 3) * 8;
            *reinterpret_cast<uint4*>(base + OAh + off) = rah[t];
            *reinterpret_cast<uint4*>(base + OAl + off) = ral[t];
        }
        if (!BTRANS) {
#pragma unroll
            for (int t = 0; t < 4; t++) {
                const int v = tid + t * 256;
                const int off = (v >> 2) * RSA + (v & 3) * 8;
                *reinterpret_cast<uint4*>(base + OBh + off) = rbh[t];
                *reinterpret_cast<uint4*>(base + OBl + off) = rbl[t];
            }
        } else {
#pragma unroll
            for (int t = 0; t < 4; t++) {
                const int v = tid + t * 256;
                const int off = (v >> 5) * RSBT + (v & 31) * 8;
                *reinterpret_cast<uint4*>(base + OBh + off) = rbh[t];
                *reinterpret_cast<uint4*>(base + OBl + off) = rbl[t];
            }
        }
    };

    // fragment addressing
    const uint32_t smB = smem_u32(sm);
    const int aRow  = wm * 64 + (lane & 7) + ((lane >> 3) & 1) * 8;
    const int aColS = ((lane >> 4) & 1) * 8;
    // non-trans B (same pattern as A)
    const int bRow  = wn * 64 + (lane & 7) + ((lane >> 4) & 1) * 8;
    const int bColS = ((lane >> 3) & 1) * 8;
    // trans B: k-row and n-col per lane
    const int btK = (lane & 7) + ((lane >> 3) & 1) * 8;
    const int btN = wn * 64 + ((lane >> 4) & 1) * 8;

    float acc[4][8][4];
#pragma unroll
    for (int i = 0; i < 4; i++)
#pragma unroll
        for (int j = 0; j < 8; j++)
#pragma unroll
            for (int c = 0; c < 4; c++) acc[i][j][c] = 0.f;

    loadT(0);
    storeT(0);
    __syncthreads();

    int s = 0;
    for (int kt = 0; kt < ktiles; kt++) {
        const bool more = (kt + 1 < ktiles);
        if (more) loadT((kt + 1) * 32);

        const uint32_t stB = smB + (uint32_t)s * (STGU * 2);
#pragma unroll
        for (int ks = 0; ks < 2; ks++) {
            uint32_t ah[4][4], al[4][4];
#pragma unroll
            for (int mt = 0; mt < 4; mt++) {
                uint32_t off = (uint32_t)(((aRow + mt * 16) * RSA) + ks * 16 + aColS) * 2;
                ldm4(ah[mt], stB + (OAh + 0) * 2 + off);
                ldm4(al[mt], stB + OAl * 2 + off);
            }
#pragma unroll
            for (int np = 0; np < 4; np++) {
                uint32_t bh[4], bl[4];
                if (!BTRANS) {
                    uint32_t off = (uint32_t)(((bRow + np * 16) * RSA) + ks * 16 + bColS) * 2;
                    ldm4(bh, stB + OBh * 2 + off);
                    ldm4(bl, stB + OBl * 2 + off);
                } else {
                    uint32_t off = (uint32_t)((ks * 16 + btK) * RSBT + btN + np * 16) * 2;
                    ldm4t(bh, stB + OBh * 2 + off);
                    ldm4t(bl, stB + OBl * 2 + off);
                }
#pragma unroll
                for (int h = 0; h < 2; h++) {
                    const int nt = np * 2 + h;
#pragma unroll
                    for (int mt = 0; mt < 4; mt++) {
                        mma16816(acc[mt][nt], ah[mt], bh[2 * h], bh[2 * h + 1]);
                        mma16816(acc[mt][nt], ah[mt], bl[2 * h], bl[2 * h + 1]);
                        mma16816(acc[mt][nt], al[mt], bh[2 * h], bh[2 * h + 1]);
                    }
                }
            }
        }
        if (more) storeT(s ^ 1);
        __syncthreads();
        s ^= 1;
    }

    // epilogue
#pragma unroll
    for (int mt = 0; mt < 4; mt++) {
        const int m = m0 + wm * 64 + mt * 16 + (lane >> 2);
#pragma unroll
        for (int nt = 0; nt < 8; nt++) {
            const int n = n0 + wn * 64 + nt * 8 + (lane & 3) * 2;
            float b0 = 0.f, b1 = 0.f;
            if (bias) { b0 = bias[n]; b1 = bias[n + 1]; }
            if (!SPLITOUT) {
                float2 v0 = {acc[mt][nt][0] + b0, acc[mt][nt][1] + b1};
                float2 v1 = {acc[mt][nt][2] + b0, acc[mt][nt][3] + b1};
                *reinterpret_cast<float2*>(&Cf[(size_t)m * ldc + n]) = v0;
                *reinterpret_cast<float2*>(&Cf[(size_t)(m + 8) * ldc + n]) = v1;
            } else {
                uint32_t h, l;
                cvt_hl(acc[mt][nt][0] + b0, acc[mt][nt][1] + b1, h, l);
                *reinterpret_cast<uint32_t*>(&Ch[(size_t)m * ldc + n]) = h;
                *reinterpret_cast<uint32_t*>(&Cl[(size_t)m * ldc + n]) = l;
                cvt_hl(acc[mt][nt][2] + b0, acc[mt][nt][3] + b1, h, l);
                *reinterpret_cast<uint32_t*>(&Ch[(size_t)(m + 8) * ldc + n]) = h;
                *reinterpret_cast<uint32_t*>(&Cl[(size_t)(m + 8) * ldc + n]) = l;
            }
        }
    }
}

#define SMEM_NT ((2 * (2 * 128 * RSA + 2 * 256 * RSA)) * 2)
#define SMEM_T  ((2 * (2 * 128 * RSA + 2 * 32 * RSBT)) * 2)

// ---------------------------------------------------------------------------
// Row-wise causal softmax; emits split-bf16 probability matrices.
// ---------------------------------------------------------------------------
__global__ __launch_bounds__(256) void softmax_causal(
    const float* __restrict__ Smat, const float* __restrict__ amask,
    u16* __restrict__ Ph, u16* __restrict__ Pl)
{
    const int i = blockIdx.x;
    const int b = blockIdx.y;
    const size_t rbase = ((size_t)b * SS + i) * SS;
    const float* row = Smat + rbase;
    const float* am = amask + (size_t)b * SS;
    const int tid = threadIdx.x;

    float vals[4];
    float mx = -1e30f;
#pragma unroll
    for (int r = 0; r < 2; r++) {
        const int j = r * 512 + tid * 2;
        float2 f = *reinterpret_cast<const float2*>(&row[j]);
        float s0 = (j     <= i) ? f.x : -10000.0f;
        float s1 = (j + 1 <= i) ? f.y : -10000.0f;
        s0 += (1.0f - am[j]) * -10000.0f;
        s1 += (1.0f - am[j + 1]) * -10000.0f;
        vals[2 * r] = s0; vals[2 * r + 1] = s1;
        mx = fmaxf(mx, fmaxf(s0, s1));
    }

    __shared__ float red[8];
#pragma unroll
    for (int o = 16; o > 0; o >>= 1) mx = fmaxf(mx, __shfl_xor_sync(0xffffffffu, mx, o));
    if ((tid & 31) == 0) red[tid >> 5] = mx;
    __syncthreads();
    mx = red[0];
#pragma unroll
    for (int w = 1; w < 8; w++) mx = fmaxf(mx, red[w]);

    float sum = 0.f;
#pragma unroll
    for (int r = 0; r < 4; r++) {
        vals[r] = __expf(vals[r] - mx);
        sum += vals[r];
    }
#pragma unroll
    for (int o = 16; o > 0; o >>= 1) sum += __shfl_xor_sync(0xffffffffu, sum, o);
    __syncthreads();
    if ((tid & 31) == 0) red[tid >> 5] = sum;
    __syncthreads();
    sum = 0.f;
#pragma unroll
    for (int w = 0; w < 8; w++) sum += red[w];

    const float inv = 1.0f / sum;
#pragma unroll
    for (int r = 0; r < 2; r++) {
        const int j = r * 512 + tid * 2;
        uint32_t h, l;
        cvt_hl(vals[2 * r] * inv, vals[2 * r + 1] * inv, h, l);
        *reinterpret_cast<uint32_t*>(&Ph[rbase + j]) = h;
        *reinterpret_cast<uint32_t*>(&Pl[rbase + j]) = l;
    }
}

// ---------------------------------------------------------------------------
__global__ void transpose_w1(const float* __restrict__ W1, float* __restrict__ W1t)
{
    int idx = blockIdx.x * 256 + threadIdx.x;
    if (idx < HH * EE) {
        int c = idx / EE;
        int e = idx % EE;
        W1t[e * HH + c] = W1[idx];
    }
}

// ---------------------------------------------------------------------------
// Fused MLP head: out = relu(X @ W1^T + b1) @ W2^T + b2
// ---------------------------------------------------------------------------
__global__ __launch_bounds__(256) void mlp_kernel(
    const float* __restrict__ X, const float* __restrict__ W1t,
    const float* __restrict__ b1, const float* __restrict__ W2,
    const float* __restrict__ b2, float* __restrict__ out)
{
    __shared__ float xs[4][EE];
    __shared__ float hs[4][HH];
    const int row0 = blockIdx.x * 4;
    const int tid = threadIdx.x;

    for (int v = tid; v < 4 * EE; v += 256)
        xs[v / EE][v % EE] = X[(size_t)(row0 + v / EE) * EE + (v % EE)];
    __syncthreads();

    const int c  = tid & 63;
    const int rr = tid >> 6;
    float a0 = 0.f, a1 = 0.f, a2 = 0.f, a3 = 0.f;
#pragma unroll 4
    for (int e = 0; e < EE; e += 4) {
        a0 += xs[rr][e + 0] * W1t[(e + 0) * HH + c];
        a1 += xs[rr][e + 1] * W1t[(e + 1) * HH + c];
        a2 += xs[rr][e + 2] * W1t[(e + 2) * HH + c];
        a3 += xs[rr][e + 3] * W1t[(e + 3) * HH + c];
    }
    float acc = b1[c] + ((a0 + a1) + (a2 + a3));
    hs[rr][c] = fmaxf(acc, 0.f);
    __syncthreads();

    if (tid < 4 * LL) {
        int r2 = tid >> 1;
        int l  = tid & 1;
        float s = b2[l];
#pragma unroll
        for (int h = 0; h < HH; h++) s += hs[r2][h] * W2[l * HH + h];
        out[(size_t)(row0 + r2) * LL + l] = s;
    }
}

// ---------------------------------------------------------------------------
extern "C" void kernel_launch(void* const* d_in, const int* in_sizes, int n_in,
                              void* d_out, int out_size)
{
    const float* hidden = (const float*)d_in[0];
    const float* amask  = (const float*)d_in[1];
    const float* Wk = (const float*)d_in[2];
    const float* bk = (const float*)d_in[3];
    const float* Wq = (const float*)d_in[4];
    const float* bq = (const float*)d_in[5];
    const float* Wv = (const float*)d_in[6];
    const float* bv = (const float*)d_in[7];
    const float* W1 = (const float*)d_in[8];
    const float* b1 = (const float*)d_in[9];
    const float* W2 = (const float*)d_in[10];
    const float* b2 = (const float*)d_in[11];
    float* out = (float*)d_out;

    u16 *hid_h, *hid_l, *wq_h, *wq_l, *wk_h, *wk_l, *wv_h, *wv_l;
    u16 *q_h, *q_l, *k_h, *k_l, *v_h, *v_l, *p_h, *p_l;
    float *sbuf, *abuf, *w1t;
    cudaGetSymbolAddress((void**)&hid_h, g_hid_h); cudaGetSymbolAddress((void**)&hid_l, g_hid_l);
    cudaGetSymbolAddress((void**)&wq_h, g_wq_h);   cudaGetSymbolAddress((void**)&wq_l, g_wq_l);
    cudaGetSymbolAddress((void**)&wk_h, g_wk_h);   cudaGetSymbolAddress((void**)&wk_l, g_wk_l);
    cudaGetSymbolAddress((void**)&wv_h, g_wv_h);   cudaGetSymbolAddress((void**)&wv_l, g_wv_l);
    cudaGetSymbolAddress((void**)&q_h, g_q_h);     cudaGetSymbolAddress((void**)&q_l, g_q_l);
    cudaGetSymbolAddress((void**)&k_h, g_k_h);     cudaGetSymbolAddress((void**)&k_l, g_k_l);
    cudaGetSymbolAddress((void**)&v_h, g_v_h);     cudaGetSymbolAddress((void**)&v_l, g_v_l);
    cudaGetSymbolAddress((void**)&p_h, g_p_h);     cudaGetSymbolAddress((void**)&p_l, g_p_l);
    cudaGetSymbolAddress((void**)&sbuf, g_s);
    cudaGetSymbolAddress((void**)&abuf, g_a);
    cudaGetSymbolAddress((void**)&w1t, g_w1t);

    cudaFuncSetAttribute((const void*)gemm_bf16<false, false, false, true>,
                         cudaFuncAttributeMaxDynamicSharedMemorySize, SMEM_NT);
    cudaFuncSetAttribute((const void*)gemm_bf16<false, true, false, false>,
                         cudaFuncAttributeMaxDynamicSharedMemorySize, SMEM_NT);
    cudaFuncSetAttribute((const void*)gemm_bf16<true, false, true, false>,
                         cudaFuncAttributeMaxDynamicSharedMemorySize, SMEM_T);

    const dim3 blk(256);

    // One-time splits: hidden + weights
    split_f32<<<2368, blk>>>((const float4*)hidden, (uint2*)hid_h, (uint2*)hid_l,
                             MM * EE / 4);
    split_f32<<<576, blk>>>((const float4*)Wq, (uint2*)wq_h, (uint2*)wq_l, EE * EE / 4);
    split_f32<<<576, blk>>>((const float4*)Wk, (uint2*)wk_h, (uint2*)wk_l, EE * EE / 4);
    split_f32<<<576, blk>>>((const float4*)Wv, (uint2*)wv_h, (uint2*)wv_l, EE * EE / 4);
    transpose_w1<<<(EE * HH + 255) / 256, blk>>>(W1, w1t);

    // Projections: q/k/v emitted directly as split-bf16 (+bias)
    gemm_bf16<false, false, false, true><<<dim3(EE / 256, MM / 128, 1), blk, SMEM_NT>>>(
        hid_h, hid_l, wq_h, wq_l, bq, nullptr, q_h, q_l, EE, EE, EE, EE, 0, 0, 0);
    gemm_bf16<false, false, false, true><<<dim3(EE / 256, MM / 128, 1), blk, SMEM_NT>>>(
        hid_h, hid_l, wk_h, wk_l, bk, nullptr, k_h, k_l, EE, EE, EE, EE, 0, 0, 0);
    gemm_bf16<false, false, false, true><<<dim3(EE / 256, MM / 128, 1), blk, SMEM_NT>>>(
        hid_h, hid_l, wv_h, wv_l, bv, nullptr, v_h, v_l, EE, EE, EE, EE, 0, 0, 0);

    // Scores (f32 out, causal tile skip)
    gemm_bf16<false, true, false, false><<<dim3(SS / 256, SS / 128, BB), blk, SMEM_NT>>>(
        q_h, q_l, k_h, k_l, nullptr, sbuf, nullptr, nullptr, EE, EE, EE, SS,
        (long long)SS * EE, (long long)SS * EE, (long long)SS * SS);

    // Softmax -> split-bf16 P
    softmax_causal<<<dim3(SS, BB), blk>>>(sbuf, amask, p_h, p_l);

    // PV: A = P (K-major), B = V [s][e] via ldmatrix.trans; K limited by causality
    gemm_bf16<true, false, true, false><<<dim3(EE / 256, SS / 128, BB), blk, SMEM_T>>>(
        p_h, p_l, v_h, v_l, nullptr, abuf, nullptr, nullptr, SS, SS, EE, EE,
        (long long)SS * SS, (long long)SS * EE, (long long)SS * EE);

    // Fused MLP head -> out [B*S, 2]
    mlp_kernel<<<MM / 4, blk>>>(abuf, w1t, b1, W2, b2, out);
}

// round 8
// speedup vs baseline: 2.0091x; 1.0283x over previous
#include <cuda_runtime.h>
#include <cstdint>

// Problem constants
#define BB 32
#define SS 1024
#define EE 768
#define HH 64
#define LL 2
#define MM (BB * SS)

typedef unsigned short u16;

// ---------------------------------------------------------------------------
// Scratch (static device allocations)
// ---------------------------------------------------------------------------
__device__ u16  g_hid_h[(size_t)MM * EE], g_hid_l[(size_t)MM * EE];
__device__ u16  g_wq_h[EE * EE], g_wq_l[EE * EE];
__device__ u16  g_wk_h[EE * EE], g_wk_l[EE * EE];
__device__ u16  g_wv_h[EE * EE], g_wv_l[EE * EE];
__device__ u16  g_q_h[(size_t)MM * EE], g_q_l[(size_t)MM * EE];
__device__ u16  g_k_h[(size_t)MM * EE], g_k_l[(size_t)MM * EE];
__device__ u16  g_v_h[(size_t)MM * EE], g_v_l[(size_t)MM * EE];
__device__ u16  g_p_h[(size_t)BB * SS * SS], g_p_l[(size_t)BB * SS * SS];
__device__ float g_s[(size_t)BB * SS * SS];
__device__ float g_a[(size_t)MM * EE];
__device__ float g_w1t[EE * HH];

// ---------------------------------------------------------------------------
// helpers
// ---------------------------------------------------------------------------
__device__ __forceinline__ uint32_t smem_u32(const void* p) {
    return (uint32_t)__cvta_generic_to_shared(p);
}
__device__ __forceinline__ void ldm4(uint32_t* r, uint32_t addr) {
    asm volatile("ldmatrix.sync.aligned.m8n8.x4.shared.b16 {%0,%1,%2,%3}, [%4];"
                 : "=r"(r[0]), "=r"(r[1]), "=r"(r[2]), "=r"(r[3]) : "r"(addr));
}
__device__ __forceinline__ void ldm4t(uint32_t* r, uint32_t addr) {
    asm volatile("ldmatrix.sync.aligned.m8n8.x4.trans.shared.b16 {%0,%1,%2,%3}, [%4];"
                 : "=r"(r[0]), "=r"(r[1]), "=r"(r[2]), "=r"(r[3]) : "r"(addr));
}
__device__ __forceinline__ void mma16816(float* d, const uint32_t* a,
                                         uint32_t b0, uint32_t b1) {
    asm volatile(
        "mma.sync.aligned.m16n8k16.row.col.f32.bf16.bf16.f32 "
        "{%0,%1,%2,%3},{%4,%5,%6,%7},{%8,%9},{%0,%1,%2,%3};"
        : "+f"(d[0]), "+f"(d[1]), "+f"(d[2]), "+f"(d[3])
        : "r"(a[0]), "r"(a[1]), "r"(a[2]), "r"(a[3]), "r"(b0), "r"(b1));
}
// hardware f32 pair -> bf16x2 (hi) + residual bf16x2 (lo); lo half = first arg
__device__ __forceinline__ uint32_t pack2(float a, float b) {
    uint32_t r;
    asm("cvt.rn.bf16x2.f32 %0, %1, %2;" : "=r"(r) : "f"(b), "f"(a));
    return r;
}
__device__ __forceinline__ void cvt_hl(float a, float b, uint32_t& h, uint32_t& l) {
    h = pack2(a, b);
    float ha = __uint_as_float(h << 16);
    float hb = __uint_as_float(h & 0xffff0000u);
    l = pack2(a - ha, b - hb);
}

// ---------------------------------------------------------------------------
// One-time f32 -> (hi, lo) bf16 split, vectorized
// ---------------------------------------------------------------------------
__global__ void split_f32(const float4* __restrict__ x, uint2* __restrict__ h,
                          uint2* __restrict__ l, int n4)
{
    for (int i = blockIdx.x * blockDim.x + threadIdx.x; i < n4;
         i += gridDim.x * blockDim.x) {
        float4 f = x[i];
        uint2 hh, ll;
        cvt_hl(f.x, f.y, hh.x, ll.x);
        cvt_hl(f.z, f.w, hh.y, ll.y);
        h[i] = hh; l[i] = ll;
    }
}

// ---------------------------------------------------------------------------
// Split-bf16 tensor-core GEMM: C[m,n] = sum_k A[m,k]*B(k,n) + bias[n]
// Operands pre-split into hi/lo bf16 in gmem; hot loop = LDG/STS/LDSM/HMMA.
// Inner MMA nest is TERM-MAJOR so same-accumulator reuse is 8 instructions
// apart (breaks the f32-accumulate RAW chain).
//   BTRANS=false: B K-major [n][k];  BTRANS=true: B [k][n] (PV), ldmatrix.trans
//   SPLITOUT: epilogue emits hi/lo bf16 arrays instead of f32
// Block 128x256x32, 8 warps (2x4), warp 64x64, double-buffered.
// ---------------------------------------------------------------------------
#define RSA 40     // A (and K-major B) smem row stride, u16
#define RSBT 264   // trans-B smem row stride, u16

template<bool BTRANS, bool CAUSAL, bool PVLIM, bool SPLITOUT>
__global__ __launch_bounds__(256, 1) void gemm_bf16(
    const u16* __restrict__ Agh, const u16* __restrict__ Agl,
    const u16* __restrict__ Bgh, const u16* __restrict__ Bgl,
    const float* __restrict__ bias,
    float* __restrict__ Cf, u16* __restrict__ Ch, u16* __restrict__ Cl,
    int K, int lda, int ldb, int ldc,
    long long sA, long long sB, long long sC)
{
    const int n0 = blockIdx.x * 256;
    const int m0 = blockIdx.y * 128;
    if (CAUSAL && n0 >= m0 + 128) return;

    Agh += (long long)blockIdx.z * sA; Agl += (long long)blockIdx.z * sA;
    Bgh += (long long)blockIdx.z * sB; Bgl += (long long)blockIdx.z * sB;
    if (SPLITOUT) {
        Ch += (long long)blockIdx.z * sC; Cl += (long long)blockIdx.z * sC;
    } else {
        Cf += (long long)blockIdx.z * sC;
    }

    int kend = PVLIM ? (m0 + 128) : K;
    const int ktiles = kend / 32;

    constexpr int ASZ = 128 * RSA;
    constexpr int BSZ = BTRANS ? 32 * RSBT : 256 * RSA;
    constexpr int OAh = 0, OAl = ASZ, OBh = 2 * ASZ, OBl = 2 * ASZ + BSZ;
    constexpr int STGU = 2 * ASZ + 2 * BSZ;

    extern __shared__ __align__(16) u16 sm[];

    const int tid  = threadIdx.x;
    const int lane = tid & 31;
    const int wid  = tid >> 5;
    const int wm   = wid >> 2;   // 0..1
    const int wn   = wid & 3;    // 0..3

    uint4 rah[2], ral[2], rbh[4], rbl[4];

    auto loadT = [&](int k0) {
#pragma unroll
        for (int t = 0; t < 2; t++) {
            const int v = tid + t * 256;           // 0..511
            const size_t g = (size_t)(m0 + (v >> 2)) * lda + k0 + (v & 3) * 8;
            rah[t] = *reinterpret_cast<const uint4*>(Agh + g);
            ral[t] = *reinterpret_cast<const uint4*>(Agl + g);
        }
        if (!BTRANS) {
#pragma unroll
            for (int t = 0; t < 4; t++) {
                const int v = tid + t * 256;       // 0..1023
                const size_t g = (size_t)(n0 + (v >> 2)) * ldb + k0 + (v & 3) * 8;
                rbh[t] = *reinterpret_cast<const uint4*>(Bgh + g);
                rbl[t] = *reinterpret_cast<const uint4*>(Bgl + g);
            }
        } else {
            // k-tile: 32 rows x 256 cols -> 1024 uint4; row = v>>5, col = (v&31)*8
#pragma unroll
            for (int t = 0; t < 4; t++) {
                const int v = tid + t * 256;
                const size_t g = (size_t)(k0 + (v >> 5)) * ldb + n0 + (v & 31) * 8;
                rbh[t] = *reinterpret_cast<const uint4*>(Bgh + g);
                rbl[t] = *reinterpret_cast<const uint4*>(Bgl + g);
            }
        }
    };

    auto storeT = [&](int s) {
        u16* base = sm + s * STGU;
#pragma unroll
        for (int t = 0; t < 2; t++) {
            const int v = tid + t * 256;
            const int off = (v >> 2) * RSA + (v & 3) * 8;
            *reinterpret_cast<uint4*>(base + OAh + off) = rah[t];
            *reinterpret_cast<uint4*>(base + OAl + off) = ral[t];
        }
        if (!BTRANS) {
#pragma unroll
            for (int t = 0; t < 4; t++) {
                const int v = tid + t * 256;
                const int off = (v >> 2) * RSA + (v & 3) * 8;
                *reinterpret_cast<uint4*>(base + OBh + off) = rbh[t];
                *reinterpret_cast<uint4*>(base + OBl + off) = rbl[t];
            }
        } else {
#pragma unroll
            for (int t = 0; t < 4; t++) {
                const int v = tid + t * 256;
                const int off = (v >> 5) * RSBT + (v & 31) * 8;
                *reinterpret_cast<uint4*>(base + OBh + off) = rbh[t];
                *reinterpret_cast<uint4*>(base + OBl + off) = rbl[t];
            }
        }
    };

    // fragment addressing
    const uint32_t smB = smem_u32(sm);
    const int aRow  = wm * 64 + (lane & 7) + ((lane >> 3) & 1) * 8;
    const int aColS = ((lane >> 4) & 1) * 8;
    // non-trans B (same pattern as A)
    const int bRow  = wn * 64 + (lane & 7) + ((lane >> 4) & 1) * 8;
    const int bColS = ((lane >> 3) & 1) * 8;
    // trans B: k-row and n-col per lane
    const int btK = (lane & 7) + ((lane >> 3) & 1) * 8;
    const int btN = wn * 64 + ((lane >> 4) & 1) * 8;

    float acc[4][8][4];
#pragma unroll
    for (int i = 0; i < 4; i++)
#pragma unroll
        for (int j = 0; j < 8; j++)
#pragma unroll
            for (int c = 0; c < 4; c++) acc[i][j][c] = 0.f;

    loadT(0);
    storeT(0);
    __syncthreads();

    int s = 0;
    for (int kt = 0; kt < ktiles; kt++) {
        const bool more = (kt + 1 < ktiles);
        if (more) loadT((kt + 1) * 32);          // LDGs fly over the MMA phase

        const uint32_t stB = smB + (uint32_t)s * (STGU * 2);
#pragma unroll
        for (int ks = 0; ks < 2; ks++) {
            uint32_t ah[4][4], al[4][4];
#pragma unroll
            for (int mt = 0; mt < 4; mt++) {
                uint32_t off = (uint32_t)(((aRow + mt * 16) * RSA) + ks * 16 + aColS) * 2;
                ldm4(ah[mt], stB + OAh * 2 + off);
                ldm4(al[mt], stB + OAl * 2 + off);
            }
#pragma unroll
            for (int np = 0; np < 4; np++) {
                uint32_t bh[4], bl[4];
                if (!BTRANS) {
                    uint32_t off = (uint32_t)(((bRow + np * 16) * RSA) + ks * 16 + bColS) * 2;
                    ldm4(bh, stB + OBh * 2 + off);
                    ldm4(bl, stB + OBl * 2 + off);
                } else {
                    uint32_t off = (uint32_t)((ks * 16 + btK) * RSBT + btN + np * 16) * 2;
                    ldm4t(bh, stB + OBh * 2 + off);
                    ldm4t(bl, stB + OBl * 2 + off);
                }
                // term-major: same accumulator reused only every 8 MMAs
#pragma unroll
                for (int h = 0; h < 2; h++)
#pragma unroll
                    for (int mt = 0; mt < 4; mt++)
                        mma16816(acc[mt][np * 2 + h], ah[mt], bh[2 * h], bh[2 * h + 1]);
#pragma unroll
                for (int h = 0; h < 2; h++)
#pragma unroll
                    for (int mt = 0; mt < 4; mt++)
                        mma16816(acc[mt][np * 2 + h], ah[mt], bl[2 * h], bl[2 * h + 1]);
#pragma unroll
                for (int h = 0; h < 2; h++)
#pragma unroll
                    for (int mt = 0; mt < 4; mt++)
                        mma16816(acc[mt][np * 2 + h], al[mt], bh[2 * h], bh[2 * h + 1]);
            }
            // hide next-stage STS under the second k-subtile's MMA block
            if (ks == 0 && more) storeT(s ^ 1);
        }
        __syncthreads();
        s ^= 1;
    }

    // epilogue
#pragma unroll
    for (int mt = 0; mt < 4; mt++) {
        const int m = m0 + wm * 64 + mt * 16 + (lane >> 2);
#pragma unroll
        for (int nt = 0; nt < 8; nt++) {
            const int n = n0 + wn * 64 + nt * 8 + (lane & 3) * 2;
            float b0 = 0.f, b1 = 0.f;
            if (bias) { b0 = bias[n]; b1 = bias[n + 1]; }
            if (!SPLITOUT) {
                float2 v0 = {acc[mt][nt][0] + b0, acc[mt][nt][1] + b1};
                float2 v1 = {acc[mt][nt][2] + b0, acc[mt][nt][3] + b1};
                *reinterpret_cast<float2*>(&Cf[(size_t)m * ldc + n]) = v0;
                *reinterpret_cast<float2*>(&Cf[(size_t)(m + 8) * ldc + n]) = v1;
            } else {
                uint32_t h, l;
                cvt_hl(acc[mt][nt][0] + b0, acc[mt][nt][1] + b1, h, l);
                *reinterpret_cast<uint32_t*>(&Ch[(size_t)m * ldc + n]) = h;
                *reinterpret_cast<uint32_t*>(&Cl[(size_t)m * ldc + n]) = l;
                cvt_hl(acc[mt][nt][2] + b0, acc[mt][nt][3] + b1, h, l);
                *reinterpret_cast<uint32_t*>(&Ch[(size_t)(m + 8) * ldc + n]) = h;
                *reinterpret_cast<uint32_t*>(&Cl[(size_t)(m + 8) * ldc + n]) = l;
            }
        }
    }
}

#define SMEM_NT ((2 * (2 * 128 * RSA + 2 * 256 * RSA)) * 2)
#define SMEM_T  ((2 * (2 * 128 * RSA + 2 * 32 * RSBT)) * 2)

// ---------------------------------------------------------------------------
// Row-wise causal softmax; emits split-bf16 probability matrices.
// ---------------------------------------------------------------------------
__global__ __launch_bounds__(256) void softmax_causal(
    const float* __restrict__ Smat, const float* __restrict__ amask,
    u16* __restrict__ Ph, u16* __restrict__ Pl)
{
    const int i = blockIdx.x;
    const int b = blockIdx.y;
    const size_t rbase = ((size_t)b * SS + i) * SS;
    const float* row = Smat + rbase;
    const float* am = amask + (size_t)b * SS;
    const int tid = threadIdx.x;

    float vals[4];
    float mx = -1e30f;
#pragma unroll
    for (int r = 0; r < 2; r++) {
        const int j = r * 512 + tid * 2;
        float2 f = *reinterpret_cast<const float2*>(&row[j]);
        float s0 = (j     <= i) ? f.x : -10000.0f;
        float s1 = (j + 1 <= i) ? f.y : -10000.0f;
        s0 += (1.0f - am[j]) * -10000.0f;
        s1 += (1.0f - am[j + 1]) * -10000.0f;
        vals[2 * r] = s0; vals[2 * r + 1] = s1;
        mx = fmaxf(mx, fmaxf(s0, s1));
    }

    __shared__ float red[8];
#pragma unroll
    for (int o = 16; o > 0; o >>= 1) mx = fmaxf(mx, __shfl_xor_sync(0xffffffffu, mx, o));
    if ((tid & 31) == 0) red[tid >> 5] = mx;
    __syncthreads();
    mx = red[0];
#pragma unroll
    for (int w = 1; w < 8; w++) mx = fmaxf(mx, red[w]);

    float sum = 0.f;
#pragma unroll
    for (int r = 0; r < 4; r++) {
        vals[r] = __expf(vals[r] - mx);
        sum += vals[r];
    }
#pragma unroll
    for (int o = 16; o > 0; o >>= 1) sum += __shfl_xor_sync(0xffffffffu, sum, o);
    __syncthreads();
    if ((tid & 31) == 0) red[tid >> 5] = sum;
    __syncthreads();
    sum = 0.f;
#pragma unroll
    for (int w = 0; w < 8; w++) sum += red[w];

    const float inv = 1.0f / sum;
#pragma unroll
    for (int r = 0; r < 2; r++) {
        const int j = r * 512 + tid * 2;
        uint32_t h, l;
        cvt_hl(vals[2 * r] * inv, vals[2 * r + 1] * inv, h, l);
        *reinterpret_cast<uint32_t*>(&Ph[rbase + j]) = h;
        *reinterpret_cast<uint32_t*>(&Pl[rbase + j]) = l;
    }
}

// ---------------------------------------------------------------------------
__global__ void transpose_w1(const float* __restrict__ W1, float* __restrict__ W1t)
{
    int idx = blockIdx.x * 256 + threadIdx.x;
    if (idx < HH * EE) {
        int c = idx / EE;
        int e = idx % EE;
        W1t[e * HH + c] = W1[idx];
    }
}

// ---------------------------------------------------------------------------
// Fused MLP head: out = relu(X @ W1^T + b1) @ W2^T + b2
// ---------------------------------------------------------------------------
__global__ __launch_bounds__(256) void mlp_kernel(
    const float* __restrict__ X, const float* __restrict__ W1t,
    const float* __restrict__ b1, const float* __restrict__ W2,
    const float* __restrict__ b2, float* __restrict__ out)
{
    __shared__ float xs[4][EE];
    __shared__ float hs[4][HH];
    const int row0 = blockIdx.x * 4;
    const int tid = threadIdx.x;

    for (int v = tid; v < 4 * EE; v += 256)
        xs[v / EE][v % EE] = X[(size_t)(row0 + v / EE) * EE + (v % EE)];
    __syncthreads();

    const int c  = tid & 63;
    const int rr = tid >> 6;
    float a0 = 0.f, a1 = 0.f, a2 = 0.f, a3 = 0.f;
#pragma unroll 4
    for (int e = 0; e < EE; e += 4) {
        a0 += xs[rr][e + 0] * W1t[(e + 0) * HH + c];
        a1 += xs[rr][e + 1] * W1t[(e + 1) * HH + c];
        a2 += xs[rr][e + 2] * W1t[(e + 2) * HH + c];
        a3 += xs[rr][e + 3] * W1t[(e + 3) * HH + c];
    }
    float acc = b1[c] + ((a0 + a1) + (a2 + a3));
    hs[rr][c] = fmaxf(acc, 0.f);
    __syncthreads();

    if (tid < 4 * LL) {
        int r2 = tid >> 1;
        int l  = tid & 1;
        float s = b2[l];
#pragma unroll
        for (int h = 0; h < HH; h++) s += hs[r2][h] * W2[l * HH + h];
        out[(size_t)(row0 + r2) * LL + l] = s;
    }
}

// ---------------------------------------------------------------------------
extern "C" void kernel_launch(void* const* d_in, const int* in_sizes, int n_in,
                              void* d_out, int out_size)
{
    const float* hidden = (const float*)d_in[0];
    const float* amask  = (const float*)d_in[1];
    const float* Wk = (const float*)d_in[2];
    const float* bk = (const float*)d_in[3];
    const float* Wq = (const float*)d_in[4];
    const float* bq = (const float*)d_in[5];
    const float* Wv = (const float*)d_in[6];
    const float* bv = (const float*)d_in[7];
    const float* W1 = (const float*)d_in[8];
    const float* b1 = (const float*)d_in[9];
    const float* W2 = (const float*)d_in[10];
    const float* b2 = (const float*)d_in[11];
    float* out = (float*)d_out;

    u16 *hid_h, *hid_l, *wq_h, *wq_l, *wk_h, *wk_l, *wv_h, *wv_l;
    u16 *q_h, *q_l, *k_h, *k_l, *v_h, *v_l, *p_h, *p_l;
    float *sbuf, *abuf, *w1t;
    cudaGetSymbolAddress((void**)&hid_h, g_hid_h); cudaGetSymbolAddress((void**)&hid_l, g_hid_l);
    cudaGetSymbolAddress((void**)&wq_h, g_wq_h);   cudaGetSymbolAddress((void**)&wq_l, g_wq_l);
    cudaGetSymbolAddress((void**)&wk_h, g_wk_h);   cudaGetSymbolAddress((void**)&wk_l, g_wk_l);
    cudaGetSymbolAddress((void**)&wv_h, g_wv_h);   cudaGetSymbolAddress((void**)&wv_l, g_wv_l);
    cudaGetSymbolAddress((void**)&q_h, g_q_h);     cudaGetSymbolAddress((void**)&q_l, g_q_l);
    cudaGetSymbolAddress((void**)&k_h, g_k_h);     cudaGetSymbolAddress((void**)&k_l, g_k_l);
    cudaGetSymbolAddress((void**)&v_h, g_v_h);     cudaGetSymbolAddress((void**)&v_l, g_v_l);
    cudaGetSymbolAddress((void**)&p_h, g_p_h);     cudaGetSymbolAddress((void**)&p_l, g_p_l);
    cudaGetSymbolAddress((void**)&sbuf, g_s);
    cudaGetSymbolAddress((void**)&abuf, g_a);
    cudaGetSymbolAddress((void**)&w1t, g_w1t);

    cudaFuncSetAttribute((const void*)gemm_bf16<false, false, false, true>,
                         cudaFuncAttributeMaxDynamicSharedMemorySize, SMEM_NT);
    cudaFuncSetAttribute((const void*)gemm_bf16<false, true, false, false>,
                         cudaFuncAttributeMaxDynamicSharedMemorySize, SMEM_NT);
    cudaFuncSetAttribute((const void*)gemm_bf16<true, false, true, false>,
                         cudaFuncAttributeMaxDynamicSharedMemorySize, SMEM_T);

    const dim3 blk(256);

    // One-time splits: hidden + weights
    split_f32<<<2368, blk>>>((const float4*)hidden, (uint2*)hid_h, (uint2*)hid_l,
                             MM * EE / 4);
    split_f32<<<576, blk>>>((const float4*)Wq, (uint2*)wq_h, (uint2*)wq_l, EE * EE / 4);
    split_f32<<<576, blk>>>((const float4*)Wk, (uint2*)wk_h, (uint2*)wk_l, EE * EE / 4);
    split_f32<<<576, blk>>>((const float4*)Wv, (uint2*)wv_h, (uint2*)wv_l, EE * EE / 4);
    transpose_w1<<<(EE * HH + 255) / 256, blk>>>(W1, w1t);

    // Projections: q/k/v emitted directly as split-bf16 (+bias)
    gemm_bf16<false, false, false, true><<<dim3(EE / 256, MM / 128, 1), blk, SMEM_NT>>>(
        hid_h, hid_l, wq_h, wq_l, bq, nullptr, q_h, q_l, EE, EE, EE, EE, 0, 0, 0);
    gemm_bf16<false, false, false, true><<<dim3(EE / 256, MM / 128, 1), blk, SMEM_NT>>>(
        hid_h, hid_l, wk_h, wk_l, bk, nullptr, k_h, k_l, EE, EE, EE, EE, 0, 0, 0);
    gemm_bf16<false, false, false, true><<<dim3(EE / 256, MM / 128, 1), blk, SMEM_NT>>>(
        hid_h, hid_l, wv_h, wv_l, bv, nullptr, v_h, v_l, EE, EE, EE, EE, 0, 0, 0);

    // Scores (f32 out, causal tile skip)
    gemm_bf16<false, true, false, false><<<dim3(SS / 256, SS / 128, BB), blk, SMEM_NT>>>(
        q_h, q_l, k_h, k_l, nullptr, sbuf, nullptr, nullptr, EE, EE, EE, SS,
        (long long)SS * EE, (long long)SS * EE, (long long)SS * SS);

    // Softmax -> split-bf16 P
    softmax_causal<<<dim3(SS, BB), blk>>>(sbuf, amask, p_h, p_l);

    // PV: A = P (K-major), B = V [s][e] via ldmatrix.trans; K limited by causality
    gemm_bf16<true, false, true, false><<<dim3(EE / 256, SS / 128, BB), blk, SMEM_T>>>(
        p_h, p_l, v_h, v_l, nullptr, abuf, nullptr, nullptr, SS, SS, EE, EE,
        (long long)SS * SS, (long long)SS * EE, (long long)SS * EE);

    // Fused MLP head -> out [B*S, 2]
    mlp_kernel<<<MM / 4, blk>>>(abuf, w1t, b1, W2, b2, out);
}

// round 9
// speedup vs baseline: 2.1064x; 1.0485x over previous
#include <cuda_runtime.h>
#include <cstdint>

// Problem constants
#define BB 32
#define SS 1024
#define EE 768
#define HH 64
#define LL 2
#define MM (BB * SS)
#define NQKV (3 * EE)        // 2304

typedef unsigned short u16;

// ---------------------------------------------------------------------------
// Scratch (static device allocations)
// ---------------------------------------------------------------------------
__device__ u16  g_hid_h[(size_t)MM * EE], g_hid_l[(size_t)MM * EE];
__device__ u16  g_wqkv_h[(size_t)NQKV * EE], g_wqkv_l[(size_t)NQKV * EE];
__device__ float g_bqkv[NQKV];
__device__ u16  g_qkv_h[(size_t)MM * NQKV], g_qkv_l[(size_t)MM * NQKV];
__device__ u16  g_p_h[(size_t)BB * SS * SS], g_p_l[(size_t)BB * SS * SS];
__device__ float g_s[(size_t)BB * SS * SS];
__device__ float g_a[(size_t)MM * EE];
__device__ float g_w1t[EE * HH];

// ---------------------------------------------------------------------------
// helpers
// ---------------------------------------------------------------------------
__device__ __forceinline__ uint32_t smem_u32(const void* p) {
    return (uint32_t)__cvta_generic_to_shared(p);
}
__device__ __forceinline__ void ldm4(uint32_t* r, uint32_t addr) {
    asm volatile("ldmatrix.sync.aligned.m8n8.x4.shared.b16 {%0,%1,%2,%3}, [%4];"
                 : "=r"(r[0]), "=r"(r[1]), "=r"(r[2]), "=r"(r[3]) : "r"(addr));
}
__device__ __forceinline__ void ldm4t(uint32_t* r, uint32_t addr) {
    asm volatile("ldmatrix.sync.aligned.m8n8.x4.trans.shared.b16 {%0,%1,%2,%3}, [%4];"
                 : "=r"(r[0]), "=r"(r[1]), "=r"(r[2]), "=r"(r[3]) : "r"(addr));
}
__device__ __forceinline__ void mma16816(float* d, const uint32_t* a,
                                         uint32_t b0, uint32_t b1) {
    asm volatile(
        "mma.sync.aligned.m16n8k16.row.col.f32.bf16.bf16.f32 "
        "{%0,%1,%2,%3},{%4,%5,%6,%7},{%8,%9},{%0,%1,%2,%3};"
        : "+f"(d[0]), "+f"(d[1]), "+f"(d[2]), "+f"(d[3])
        : "r"(a[0]), "r"(a[1]), "r"(a[2]), "r"(a[3]), "r"(b0), "r"(b1));
}
// hardware f32 pair -> bf16x2 (hi) + residual bf16x2 (lo); lo half = first arg
__device__ __forceinline__ uint32_t pack2(float a, float b) {
    uint32_t r;
    asm("cvt.rn.bf16x2.f32 %0, %1, %2;" : "=r"(r) : "f"(b), "f"(a));
    return r;
}
__device__ __forceinline__ void cvt_hl(float a, float b, uint32_t& h, uint32_t& l) {
    h = pack2(a, b);
    float ha = __uint_as_float(h << 16);
    float hb = __uint_as_float(h & 0xffff0000u);
    l = pack2(a - ha, b - hb);
}

// ---------------------------------------------------------------------------
// One-time f32 -> (hi, lo) bf16 split, vectorized
// ---------------------------------------------------------------------------
__global__ void split_f32(const float4* __restrict__ x, uint2* __restrict__ h,
                          uint2* __restrict__ l, int n4)
{
    for (int i = blockIdx.x * blockDim.x + threadIdx.x; i < n4;
         i += gridDim.x * blockDim.x) {
        float4 f = x[i];
        uint2 hh, ll;
        cvt_hl(f.x, f.y, hh.x, ll.x);
        cvt_hl(f.z, f.w, hh.y, ll.y);
        h[i] = hh; l[i] = ll;
    }
}

__global__ void concat_bias(const float* __restrict__ bq, const float* __restrict__ bk,
                            const float* __restrict__ bv, float* __restrict__ o)
{
    int i = blockIdx.x * 256 + threadIdx.x;
    if (i < EE) { o[i] = bq[i]; o[i + EE] = bk[i]; o[i + 2 * EE] = bv[i]; }
}

// ---------------------------------------------------------------------------
// Split-bf16 tensor-core GEMM: C[m,n] = sum_k A[m,k]*B(k,n) + bias[n]
// Term-major MMA nest; warp-level causal/PV zero-block skipping.
//   BTRANS=false: B K-major [n][k];  BTRANS=true: B [k][n] (PV), ldmatrix.trans
//   SPLITOUT: epilogue emits hi/lo bf16 arrays instead of f32
// Block 128x256x32, 8 warps (2x4), warp 64x64, double-buffered.
// ---------------------------------------------------------------------------
#define RSA 40     // A (and K-major B) smem row stride, u16
#define RSBT 264   // trans-B smem row stride, u16

template<bool BTRANS, bool CAUSAL, bool PVLIM, bool SPLITOUT>
__global__ __launch_bounds__(256, 1) void gemm_bf16(
    const u16* __restrict__ Agh, const u16* __restrict__ Agl,
    const u16* __restrict__ Bgh, const u16* __restrict__ Bgl,
    const float* __restrict__ bias,
    float* __restrict__ Cf, u16* __restrict__ Ch, u16* __restrict__ Cl,
    int K, int lda, int ldb, int ldc,
    long long sA, long long sB, long long sC)
{
    const int n0 = blockIdx.x * 256;
    const int m0 = blockIdx.y * 128;
    if (CAUSAL && n0 >= m0 + 128) return;

    Agh += (long long)blockIdx.z * sA; Agl += (long long)blockIdx.z * sA;
    Bgh += (long long)blockIdx.z * sB; Bgl += (long long)blockIdx.z * sB;
    if (SPLITOUT) {
        Ch += (long long)blockIdx.z * sC; Cl += (long long)blockIdx.z * sC;
    } else {
        Cf += (long long)blockIdx.z * sC;
    }

    int kend = PVLIM ? (m0 + 128) : K;
    const int ktiles = kend / 32;

    constexpr int ASZ = 128 * RSA;
    constexpr int BSZ = BTRANS ? 32 * RSBT : 256 * RSA;
    constexpr int OAh = 0, OAl = ASZ, OBh = 2 * ASZ, OBl = 2 * ASZ + BSZ;
    constexpr int STGU = 2 * ASZ + 2 * BSZ;

    extern __shared__ __align__(16) u16 sm[];

    const int tid  = threadIdx.x;
    const int lane = tid & 31;
    const int wid  = tid >> 5;
    const int wm   = wid >> 2;   // 0..1
    const int wn   = wid & 3;    // 0..3

    const int wmBase = m0 + wm * 64;   // warp's first m row
    const int wnBase = n0 + wn * 64;   // warp's first n col

    uint4 rah[2], ral[2], rbh[4], rbl[4];

    auto loadT = [&](int k0) {
#pragma unroll
        for (int t = 0; t < 2; t++) {
            const int v = tid + t * 256;           // 0..511
            const size_t g = (size_t)(m0 + (v >> 2)) * lda + k0 + (v & 3) * 8;
            rah[t] = *reinterpret_cast<const uint4*>(Agh + g);
            ral[t] = *reinterpret_cast<const uint4*>(Agl + g);
        }
        if (!BTRANS) {
#pragma unroll
            for (int t = 0; t < 4; t++) {
                const int v = tid + t * 256;       // 0..1023
                const size_t g = (size_t)(n0 + (v >> 2)) * ldb + k0 + (v & 3) * 8;
                rbh[t] = *reinterpret_cast<const uint4*>(Bgh + g);
                rbl[t] = *reinterpret_cast<const uint4*>(Bgl + g);
            }
        } else {
            // k-tile: 32 rows x 256 cols -> 1024 uint4; row = v>>5, col = (v&31)*8
#pragma unroll
            for (int t = 0; t < 4; t++) {
                const int v = tid + t * 256;
                const size_t g = (size_t)(k0 + (v >> 5)) * ldb + n0 + (v & 31) * 8;
                rbh[t] = *reinterpret_cast<const uint4*>(Bgh + g);
                rbl[t] = *reinterpret_cast<const uint4*>(Bgl + g);
            }
        }
    };

    auto storeT = [&](int s) {
        u16* base = sm + s * STGU;
#pragma unroll
        for (int t = 0; t < 2; t++) {
            const int v = tid + t * 256;
            const int off = (v >> 2) * RSA + (v & 3) * 8;
            *reinterpret_cast<uint4*>(base + OAh + off) = rah[t];
            *reinterpret_cast<uint4*>(base + OAl + off) = ral[t];
        }
        if (!BTRANS) {
#pragma unroll
            for (int t = 0; t < 4; t++) {
                const int v = tid + t * 256;
                const int off = (v >> 2) * RSA + (v & 3) * 8;
                *reinterpret_cast<uint4*>(base + OBh + off) = rbh[t];
                *reinterpret_cast<uint4*>(base + OBl + off) = rbl[t];
            }
        } else {
#pragma unroll
            for (int t = 0; t < 4; t++) {
                const int v = tid + t * 256;
                const int off = (v >> 5) * RSBT + (v & 31) * 8;
                *reinterpret_cast<uint4*>(base + OBh + off) = rbh[t];
                *reinterpret_cast<uint4*>(base + OBl + off) = rbl[t];
            }
        }
    };

    // fragment addressing
    const uint32_t smB = smem_u32(sm);
    const int aRow  = wm * 64 + (lane & 7) + ((lane >> 3) & 1) * 8;
    const int aColS = ((lane >> 4) & 1) * 8;
    const int bRow  = wn * 64 + (lane & 7) + ((lane >> 4) & 1) * 8;
    const int bColS = ((lane >> 3) & 1) * 8;
    const int btK = (lane & 7) + ((lane >> 3) & 1) * 8;
    const int btN = wn * 64 + ((lane >> 4) & 1) * 8;

    float acc[4][8][4];
#pragma unroll
    for (int i = 0; i < 4; i++)
#pragma unroll
        for (int j = 0; j < 8; j++)
#pragma unroll
            for (int c = 0; c < 4; c++) acc[i][j][c] = 0.f;

    loadT(0);
    storeT(0);
    __syncthreads();

    int s = 0;
    for (int kt = 0; kt < ktiles; kt++) {
        const bool more = (kt + 1 < ktiles);
        if (more) loadT((kt + 1) * 32);          // LDGs fly over the MMA phase

        const uint32_t stB = smB + (uint32_t)s * (STGU * 2);
#pragma unroll
        for (int ks = 0; ks < 2; ks++) {
            // PV: this warp's P rows are all-zero for k > wmBase+63 -> skip.
            const bool wactive = !PVLIM || (kt * 32 + ks * 16 <= wmBase + 63);
            if (wactive) {
                uint32_t ah[4][4], al[4][4];
#pragma unroll
                for (int mt = 0; mt < 4; mt++) {
                    uint32_t off = (uint32_t)(((aRow + mt * 16) * RSA) + ks * 16 + aColS) * 2;
                    ldm4(ah[mt], stB + OAh * 2 + off);
                    ldm4(al[mt], stB + OAl * 2 + off);
                }
#pragma unroll
                for (int np = 0; np < 4; np++) {
                    // scores: skip n-groups fully above the causal diagonal
                    const bool np_active = !CAUSAL || (wnBase + np * 16 <= wmBase + 63);
                    if (!np_active) continue;
                    uint32_t bh[4], bl[4];
                    if (!BTRANS) {
                        uint32_t off = (uint32_t)(((bRow + np * 16) * RSA) + ks * 16 + bColS) * 2;
                        ldm4(bh, stB + OBh * 2 + off);
                        ldm4(bl, stB + OBl * 2 + off);
                    } else {
                        uint32_t off = (uint32_t)((ks * 16 + btK) * RSBT + btN + np * 16) * 2;
                        ldm4t(bh, stB + OBh * 2 + off);
                        ldm4t(bl, stB + OBl * 2 + off);
                    }
                    // term-major: same accumulator reused only every few MMAs
#pragma unroll
                    for (int h = 0; h < 2; h++)
#pragma unroll
                        for (int mt = 0; mt < 4; mt++)
                            if (!CAUSAL || (wnBase + (np * 2 + h) * 8 <= wmBase + mt * 16 + 15))
                                mma16816(acc[mt][np * 2 + h], ah[mt], bh[2 * h], bh[2 * h + 1]);
#pragma unroll
                    for (int h = 0; h < 2; h++)
#pragma unroll
                        for (int mt = 0; mt < 4; mt++)
                            if (!CAUSAL || (wnBase + (np * 2 + h) * 8 <= wmBase + mt * 16 + 15))
                                mma16816(acc[mt][np * 2 + h], ah[mt], bl[2 * h], bl[2 * h + 1]);
#pragma unroll
                    for (int h = 0; h < 2; h++)
#pragma unroll
                        for (int mt = 0; mt < 4; mt++)
                            if (!CAUSAL || (wnBase + (np * 2 + h) * 8 <= wmBase + mt * 16 + 15))
                                mma16816(acc[mt][np * 2 + h], al[mt], bh[2 * h], bh[2 * h + 1]);
                }
            }
            // hide next-stage STS under the second k-subtile's MMA block
            if (ks == 0 && more) storeT(s ^ 1);
        }
        __syncthreads();
        s ^= 1;
    }

    // epilogue
#pragma unroll
    for (int mt = 0; mt < 4; mt++) {
        const int m = m0 + wm * 64 + mt * 16 + (lane >> 2);
#pragma unroll
        for (int nt = 0; nt < 8; nt++) {
            const int n = n0 + wn * 64 + nt * 8 + (lane & 3) * 2;
            float b0 = 0.f, b1 = 0.f;
            if (bias) { b0 = bias[n]; b1 = bias[n + 1]; }
            if (!SPLITOUT) {
                float2 v0 = {acc[mt][nt][0] + b0, acc[mt][nt][1] + b1};
                float2 v1 = {acc[mt][nt][2] + b0, acc[mt][nt][3] + b1};
                *reinterpret_cast<float2*>(&Cf[(size_t)m * ldc + n]) = v0;
                *reinterpret_cast<float2*>(&Cf[(size_t)(m + 8) * ldc + n]) = v1;
            } else {
                uint32_t h, l;
                cvt_hl(acc[mt][nt][0] + b0, acc[mt][nt][1] + b1, h, l);
                *reinterpret_cast<uint32_t*>(&Ch[(size_t)m * ldc + n]) = h;
                *reinterpret_cast<uint32_t*>(&Cl[(size_t)m * ldc + n]) = l;
                cvt_hl(acc[mt][nt][2] + b0, acc[mt][nt][3] + b1, h, l);
                *reinterpret_cast<uint32_t*>(&Ch[(size_t)(m + 8) * ldc + n]) = h;
                *reinterpret_cast<uint32_t*>(&Cl[(size_t)(m + 8) * ldc + n]) = l;
            }
        }
    }
}

#define SMEM_NT ((2 * (2 * 128 * RSA + 2 * 256 * RSA)) * 2)
#define SMEM_T  ((2 * (2 * 128 * RSA + 2 * 32 * RSBT)) * 2)

// ---------------------------------------------------------------------------
// Row-wise causal softmax; emits split-bf16 probability matrices.
// ---------------------------------------------------------------------------
__global__ __launch_bounds__(256) void softmax_causal(
    const float* __restrict__ Smat, const float* __restrict__ amask,
    u16* __restrict__ Ph, u16* __restrict__ Pl)
{
    const int i = blockIdx.x;
    const int b = blockIdx.y;
    const size_t rbase = ((size_t)b * SS + i) * SS;
    const float* row = Smat + rbase;
    const float* am = amask + (size_t)b * SS;
    const int tid = threadIdx.x;

    float vals[4];
    float mx = -1e30f;
#pragma unroll
    for (int r = 0; r < 2; r++) {
        const int j = r * 512 + tid * 2;
        float2 f = *reinterpret_cast<const float2*>(&row[j]);
        float s0 = (j     <= i) ? f.x : -10000.0f;
        float s1 = (j + 1 <= i) ? f.y : -10000.0f;
        s0 += (1.0f - am[j]) * -10000.0f;
        s1 += (1.0f - am[j + 1]) * -10000.0f;
        vals[2 * r] = s0; vals[2 * r + 1] = s1;
        mx = fmaxf(mx, fmaxf(s0, s1));
    }

    __shared__ float red[8];
#pragma unroll
    for (int o = 16; o > 0; o >>= 1) mx = fmaxf(mx, __shfl_xor_sync(0xffffffffu, mx, o));
    if ((tid & 31) == 0) red[tid >> 5] = mx;
    __syncthreads();
    mx = red[0];
#pragma unroll
    for (int w = 1; w < 8; w++) mx = fmaxf(mx, red[w]);

    float sum = 0.f;
#pragma unroll
    for (int r = 0; r < 4; r++) {
        vals[r] = __expf(vals[r] - mx);
        sum += vals[r];
    }
#pragma unroll
    for (int o = 16; o > 0; o >>= 1) sum += __shfl_xor_sync(0xffffffffu, sum, o);
    __syncthreads();
    if ((tid & 31) == 0) red[tid >> 5] = sum;
    __syncthreads();
    sum = 0.f;
#pragma unroll
    for (int w = 0; w < 8; w++) sum += red[w];

    const float inv = 1.0f / sum;
#pragma unroll
    for (int r = 0; r < 2; r++) {
        const int j = r * 512 + tid * 2;
        uint32_t h, l;
        cvt_hl(vals[2 * r] * inv, vals[2 * r + 1] * inv, h, l);
        *reinterpret_cast<uint32_t*>(&Ph[rbase + j]) = h;
        *reinterpret_cast<uint32_t*>(&Pl[rbase + j]) = l;
    }
}

// ---------------------------------------------------------------------------
__global__ void transpose_w1(const float* __restrict__ W1, float* __restrict__ W1t)
{
    int idx = blockIdx.x * 256 + threadIdx.x;
    if (idx < HH * EE) {
        int c = idx / EE;
        int e = idx % EE;
        W1t[e * HH + c] = W1[idx];
    }
}

// ---------------------------------------------------------------------------
// Fused MLP head: out = relu(X @ W1^T + b1) @ W2^T + b2
// ---------------------------------------------------------------------------
__global__ __launch_bounds__(256) void mlp_kernel(
    const float* __restrict__ X, const float* __restrict__ W1t,
    const float* __restrict__ b1, const float* __restrict__ W2,
    const float* __restrict__ b2, float* __restrict__ out)
{
    __shared__ float xs[4][EE];
    __shared__ float hs[4][HH];
    const int row0 = blockIdx.x * 4;
    const int tid = threadIdx.x;

    for (int v = tid; v < 4 * EE; v += 256)
        xs[v / EE][v % EE] = X[(size_t)(row0 + v / EE) * EE + (v % EE)];
    __syncthreads();

    const int c  = tid & 63;
    const int rr = tid >> 6;
    float a0 = 0.f, a1 = 0.f, a2 = 0.f, a3 = 0.f;
#pragma unroll 4
    for (int e = 0; e < EE; e += 4) {
        a0 += xs[rr][e + 0] * W1t[(e + 0) * HH + c];
        a1 += xs[rr][e + 1] * W1t[(e + 1) * HH + c];
        a2 += xs[rr][e + 2] * W1t[(e + 2) * HH + c];
        a3 += xs[rr][e + 3] * W1t[(e + 3) * HH + c];
    }
    float acc = b1[c] + ((a0 + a1) + (a2 + a3));
    hs[rr][c] = fmaxf(acc, 0.f);
    __syncthreads();

    if (tid < 4 * LL) {
        int r2 = tid >> 1;
        int l  = tid & 1;
        float s = b2[l];
#pragma unroll
        for (int h = 0; h < HH; h++) s += hs[r2][h] * W2[l * HH + h];
        out[(size_t)(row0 + r2) * LL + l] = s;
    }
}

// ---------------------------------------------------------------------------
extern "C" void kernel_launch(void* const* d_in, const int* in_sizes, int n_in,
                              void* d_out, int out_size)
{
    const float* hidden = (const float*)d_in[0];
    const float* amask  = (const float*)d_in[1];
    const float* Wk = (const float*)d_in[2];
    const float* bk = (const float*)d_in[3];
    const float* Wq = (const float*)d_in[4];
    const float* bq = (const float*)d_in[5];
    const float* Wv = (const float*)d_in[6];
    const float* bv = (const float*)d_in[7];
    const float* W1 = (const float*)d_in[8];
    const float* b1 = (const float*)d_in[9];
    const float* W2 = (const float*)d_in[10];
    const float* b2 = (const float*)d_in[11];
    float* out = (float*)d_out;

    u16 *hid_h, *hid_l, *wqkv_h, *wqkv_l, *qkv_h, *qkv_l, *p_h, *p_l;
    float *bqkv, *sbuf, *abuf, *w1t;
    cudaGetSymbolAddress((void**)&hid_h, g_hid_h); cudaGetSymbolAddress((void**)&hid_l, g_hid_l);
    cudaGetSymbolAddress((void**)&wqkv_h, g_wqkv_h); cudaGetSymbolAddress((void**)&wqkv_l, g_wqkv_l);
    cudaGetSymbolAddress((void**)&bqkv, g_bqkv);
    cudaGetSymbolAddress((void**)&qkv_h, g_qkv_h); cudaGetSymbolAddress((void**)&qkv_l, g_qkv_l);
    cudaGetSymbolAddress((void**)&p_h, g_p_h);     cudaGetSymbolAddress((void**)&p_l, g_p_l);
    cudaGetSymbolAddress((void**)&sbuf, g_s);
    cudaGetSymbolAddress((void**)&abuf, g_a);
    cudaGetSymbolAddress((void**)&w1t, g_w1t);

    cudaFuncSetAttribute((const void*)gemm_bf16<false, false, false, true>,
                         cudaFuncAttributeMaxDynamicSharedMemorySize, SMEM_NT);
    cudaFuncSetAttribute((const void*)gemm_bf16<false, true, false, false>,
                         cudaFuncAttributeMaxDynamicSharedMemorySize, SMEM_NT);
    cudaFuncSetAttribute((const void*)gemm_bf16<true, false, true, false>,
                         cudaFuncAttributeMaxDynamicSharedMemorySize, SMEM_T);

    const dim3 blk(256);

    // One-time splits: hidden + concatenated QKV weights (Wq|Wk|Wv rows)
    split_f32<<<2368, blk>>>((const float4*)hidden, (uint2*)hid_h, (uint2*)hid_l,
                             MM * EE / 4);
    split_f32<<<576, blk>>>((const float4*)Wq, (uint2*)wqkv_h, (uint2*)wqkv_l,
                            EE * EE / 4);
    split_f32<<<576, blk>>>((const float4*)Wk,
                            (uint2*)(wqkv_h + (size_t)EE * EE),
                            (uint2*)(wqkv_l + (size_t)EE * EE), EE * EE / 4);
    split_f32<<<576, blk>>>((const float4*)Wv,
                            (uint2*)(wqkv_h + 2 * (size_t)EE * EE),
                            (uint2*)(wqkv_l + 2 * (size_t)EE * EE), EE * EE / 4);
    concat_bias<<<3, blk>>>(bq, bk, bv, bqkv);
    transpose_w1<<<(EE * HH + 255) / 256, blk>>>(W1, w1t);

    // Fused QKV projection: [M, 2304] = hidden @ [Wq|Wk|Wv]^T + bias, split out
    gemm_bf16<false, false, false, true><<<dim3(NQKV / 256, MM / 128, 1), blk, SMEM_NT>>>(
        hid_h, hid_l, wqkv_h, wqkv_l, bqkv, nullptr, qkv_h, qkv_l,
        EE, EE, EE, NQKV, 0, 0, 0);

    // Scores: q = cols [0,768), k = cols [768,1536) of qkv (strided views)
    gemm_bf16<false, true, false, false><<<dim3(SS / 256, SS / 128, BB), blk, SMEM_NT>>>(
        qkv_h, qkv_l, qkv_h + EE, qkv_l + EE, nullptr, sbuf, nullptr, nullptr,
        EE, NQKV, NQKV, SS,
        (long long)SS * NQKV, (long long)SS * NQKV, (long long)SS * SS);

    // Softmax -> split-bf16 P
    softmax_causal<<<dim3(SS, BB), blk>>>(sbuf, amask, p_h, p_l);

    // PV: A = P (K-major), B = V = cols [1536,2304) of qkv, [s][e] via trans
    gemm_bf16<true, false, true, false><<<dim3(EE / 256, SS / 128, BB), blk, SMEM_T>>>(
        p_h, p_l, qkv_h + 2 * EE, qkv_l + 2 * EE, nullptr, abuf, nullptr, nullptr,
        SS, SS, NQKV, EE,
        (long long)SS * SS, (long long)SS * NQKV, (long long)SS * EE);

    // Fused MLP head -> out [B*S, 2]
    mlp_kernel<<<MM / 4, blk>>>(abuf, w1t, b1, W2, b2, out);
}